// round 1
// baseline (speedup 1.0000x reference)
#include <cuda_runtime.h>
#include <cstdint>

#define N_REAL 7225      // 85*85 patches
#define NP     7296      // padded to 57*128
#define D_REAL 2331      // 259*9
#define LD     2336      // padded K (mult of 8, 16B-aligned rows)
#define NH     85

// ---------------- scratch (static device globals; no allocation) ------------
__device__ float g_styleP[NP * LD];
__device__ float g_imgP[NP * LD];
__device__ float g_sninv[NP];
__device__ unsigned long long g_best[NP];
__device__ double g_acc;

// ---------------- f32x2 helpers (sm_100a-family packed fp32) ----------------
__device__ __forceinline__ unsigned long long pack2(float x) {
    unsigned long long r;
    asm("mov.b64 %0, {%1, %1};" : "=l"(r) : "f"(x));
    return r;
}
__device__ __forceinline__ void ffma2(unsigned long long &d, unsigned long long a,
                                      unsigned long long b) {
    asm("fma.rn.f32x2 %0, %1, %2, %0;" : "+l"(d) : "l"(a), "l"(b));
}
__device__ __forceinline__ void unpack2(unsigned long long v, float &lo, float &hi) {
    asm("mov.b64 {%0, %1}, %2;" : "=f"(lo), "=f"(hi) : "l"(v));
}

// monotone float -> uint encoding (order-preserving for all finite floats)
__device__ __forceinline__ unsigned int encf(float f) {
    unsigned int u = __float_as_uint(f);
    unsigned int mask = (unsigned int)(-(int)(u >> 31)) | 0x80000000u;
    return u ^ mask;
}

__device__ __forceinline__ float block_reduce_sum(float v) {
    __shared__ float sh[32];
    int lane = threadIdx.x & 31, w = threadIdx.x >> 5;
    #pragma unroll
    for (int o = 16; o; o >>= 1) v += __shfl_xor_sync(0xffffffffu, v, o);
    if (lane == 0) sh[w] = v;
    __syncthreads();
    if (w == 0) {
        v = (lane < (int)(blockDim.x >> 5)) ? sh[lane] : 0.f;
        #pragma unroll
        for (int o = 16; o; o >>= 1) v += __shfl_xor_sync(0xffffffffu, v, o);
    }
    return v;  // valid in thread 0
}

// ---------------- init ------------------------------------------------------
__global__ void init_kernel() {
    int t = blockIdx.x * blockDim.x + threadIdx.x;
    if (t < NP) g_best[t] = 0ull;
    if (t == 0) g_acc = 0.0;
}

// ---------------- pack: build patch matrix rows [NP][LD] --------------------
// dst[i][d]; d = c*9 + py*3 + px ; i = ph*85 + pw
// c<256 -> resp[c, ph*3+py, pw*3+px]; c>=256 -> 50 * avgpool4(map[c-256])
__global__ void pack_kernel(const float* __restrict__ resp,
                            const float* __restrict__ map,
                            float* __restrict__ dst) {
    int i = blockIdx.x;
    int ph = i / NH, pw = i - ph * NH;
    bool valid = (i < N_REAL);
    float* drow = dst + (size_t)i * LD;
    for (int d = threadIdx.x; d < LD; d += blockDim.x) {
        float v = 0.f;
        if (valid && d < D_REAL) {
            int c = d / 9, rem = d - c * 9;
            int py = rem / 3, px = rem - py * 3;
            int row = ph * 3 + py, col = pw * 3 + px;
            if (c < 256) {
                v = resp[((size_t)c * 256 + row) * 256 + col];
            } else {
                int m = c - 256;
                const float* mp = map + (size_t)m * 1024 * 1024 + (size_t)(row * 4) * 1024 + col * 4;
                float s = 0.f;
                #pragma unroll
                for (int u = 0; u < 4; u++)
                    #pragma unroll
                    for (int w = 0; w < 4; w++) s += mp[u * 1024 + w];
                v = s * (50.0f / 16.0f);   // 50 * channel_count(=1) * mean
            }
        }
        drow[d] = v;
    }
}

// ---------------- style patch norms ----------------------------------------
__global__ void norm_kernel() {
    int j = blockIdx.x;
    const float4* row = (const float4*)(g_styleP + (size_t)j * LD);
    float s = 0.f;
    for (int t = threadIdx.x; t < LD / 4; t += blockDim.x) {
        float4 v = row[t];
        s += v.x * v.x + v.y * v.y + v.z * v.z + v.w * v.w;
    }
    s = block_reduce_sum(s);
    if (threadIdx.x == 0) g_sninv[j] = (j < N_REAL) ? rsqrtf(s) : 0.f;
}

// ---------------- GEMM (128x128x8 tile) + fused argmax ----------------------
// S[i][j] = dot(styleP[i], imgP[j]) * sninv[j]; best[i] = argmax_j (fused)
#define BM 128
#define BN 128
#define KT 8

__global__ void __launch_bounds__(256, 2)
gemm_argmax_kernel() {
    __shared__ float As[KT][BM];
    __shared__ float Bs[KT][BN];

    const float* __restrict__ A = g_styleP;   // rows i (style)
    const float* __restrict__ B = g_imgP;     // rows j (img)

    int i0 = blockIdx.y * BM;
    int j0 = blockIdx.x * BN;
    int t = threadIdx.x;
    int tx = t & 15, ty = t >> 4;
    int lrow = t >> 1, lk = (t & 1) * 4;

    const float* Aptr = A + (size_t)(i0 + lrow) * LD + lk;
    const float* Bptr = B + (size_t)(j0 + lrow) * LD + lk;

    unsigned long long acc[8][4];
    #pragma unroll
    for (int a = 0; a < 8; a++)
        #pragma unroll
        for (int q = 0; q < 4; q++) acc[a][q] = 0ull;  // bits of (0.f, 0.f)

    float4 av = *(const float4*)(Aptr);
    float4 bv = *(const float4*)(Bptr);

    for (int k0 = 0; k0 < LD; k0 += KT) {
        __syncthreads();
        As[lk + 0][lrow] = av.x; As[lk + 1][lrow] = av.y;
        As[lk + 2][lrow] = av.z; As[lk + 3][lrow] = av.w;
        Bs[lk + 0][lrow] = bv.x; Bs[lk + 1][lrow] = bv.y;
        Bs[lk + 2][lrow] = bv.z; Bs[lk + 3][lrow] = bv.w;
        __syncthreads();

        if (k0 + KT < LD) {                 // prefetch next tile during compute
            av = *(const float4*)(Aptr + k0 + KT);
            bv = *(const float4*)(Bptr + k0 + KT);
        }

        #pragma unroll
        for (int k = 0; k < KT; k++) {
            float4 a0 = *(const float4*)(&As[k][ty << 3]);
            float4 a1 = *(const float4*)(&As[k][(ty << 3) + 4]);
            const unsigned long long* bp =
                (const unsigned long long*)(&Bs[k][tx << 3]);
            unsigned long long b0 = bp[0], b1 = bp[1], b2 = bp[2], b3 = bp[3];
            unsigned long long aa;
            aa = pack2(a0.x);
            ffma2(acc[0][0], aa, b0); ffma2(acc[0][1], aa, b1);
            ffma2(acc[0][2], aa, b2); ffma2(acc[0][3], aa, b3);
            aa = pack2(a0.y);
            ffma2(acc[1][0], aa, b0); ffma2(acc[1][1], aa, b1);
            ffma2(acc[1][2], aa, b2); ffma2(acc[1][3], aa, b3);
            aa = pack2(a0.z);
            ffma2(acc[2][0], aa, b0); ffma2(acc[2][1], aa, b1);
            ffma2(acc[2][2], aa, b2); ffma2(acc[2][3], aa, b3);
            aa = pack2(a0.w);
            ffma2(acc[3][0], aa, b0); ffma2(acc[3][1], aa, b1);
            ffma2(acc[3][2], aa, b2); ffma2(acc[3][3], aa, b3);
            aa = pack2(a1.x);
            ffma2(acc[4][0], aa, b0); ffma2(acc[4][1], aa, b1);
            ffma2(acc[4][2], aa, b2); ffma2(acc[4][3], aa, b3);
            aa = pack2(a1.y);
            ffma2(acc[5][0], aa, b0); ffma2(acc[5][1], aa, b1);
            ffma2(acc[5][2], aa, b2); ffma2(acc[5][3], aa, b3);
            aa = pack2(a1.z);
            ffma2(acc[6][0], aa, b0); ffma2(acc[6][1], aa, b1);
            ffma2(acc[6][2], aa, b2); ffma2(acc[6][3], aa, b3);
            aa = pack2(a1.w);
            ffma2(acc[7][0], aa, b0); ffma2(acc[7][1], aa, b1);
            ffma2(acc[7][2], aa, b2); ffma2(acc[7][3], aa, b3);
        }
    }

    // ---- epilogue: scale by sninv[j], per-i argmax over this block's j ----
    int jbase = j0 + (tx << 3);
    float sn[8];
    #pragma unroll
    for (int b = 0; b < 8; b++)
        sn[b] = (jbase + b < N_REAL) ? g_sninv[jbase + b] : 0.f;

    #pragma unroll
    for (int ii = 0; ii < 8; ii++) {
        unsigned long long key = 0ull;
        #pragma unroll
        for (int q = 0; q < 4; q++) {
            float lo, hi;
            unpack2(acc[ii][q], lo, hi);
            int jl = jbase + 2 * q, jh = jl + 1;
            if (jl < N_REAL) {
                unsigned long long k =
                    ((unsigned long long)encf(lo * sn[2 * q]) << 32) |
                    (unsigned long long)(0xFFFFFFFFu - (unsigned)jl);
                if (k > key) key = k;
            }
            if (jh < N_REAL) {
                unsigned long long k =
                    ((unsigned long long)encf(hi * sn[2 * q + 1]) << 32) |
                    (unsigned long long)(0xFFFFFFFFu - (unsigned)jh);
                if (k > key) key = k;
            }
        }
        // reduce across the 16 tx-lanes (contiguous within half-warp)
        #pragma unroll
        for (int o = 1; o < 16; o <<= 1) {
            unsigned long long other = __shfl_xor_sync(0xffffffffu, key, o);
            if (other > key) key = other;
        }
        int i = i0 + (ty << 3) + ii;
        if (tx == 0 && i < N_REAL) atomicMax(&g_best[i], key);
    }
}

// ---------------- loss ------------------------------------------------------
__global__ void loss_kernel() {
    int i = blockIdx.x;  // 0..N_REAL-1
    unsigned int nearest = 0xFFFFFFFFu - (unsigned int)(g_best[i] & 0xFFFFFFFFull);
    const float4* ir = (const float4*)(g_imgP + (size_t)i * LD);
    const float4* sr = (const float4*)(g_styleP + (size_t)nearest * LD);
    float s = 0.f;
    for (int t = threadIdx.x; t < LD / 4; t += blockDim.x) {
        float4 a = ir[t], b = sr[t];
        float dx = a.x - b.x, dy = a.y - b.y, dz = a.z - b.z, dw = a.w - b.w;
        s += dx * dx + dy * dy + dz * dz + dw * dw;  // pad rows are 0 in both
    }
    s = block_reduce_sum(s);
    if (threadIdx.x == 0) atomicAdd(&g_acc, (double)s);
}

__global__ void finalize_kernel(float* out) {
    if (threadIdx.x == 0)
        out[0] = (float)(g_acc / ((double)D_REAL * (double)N_REAL));
}

// ---------------- launch ----------------------------------------------------
extern "C" void kernel_launch(void* const* d_in, const int* in_sizes, int n_in,
                              void* d_out, int out_size) {
    // identify inputs by size (dict order: style_resp, style_map, output_map, model_resp)
    const float* bigs[2] = {nullptr, nullptr};
    const float* smalls[2] = {nullptr, nullptr};
    int bi = 0, si = 0;
    for (int k = 0; k < n_in; k++) {
        if (in_sizes[k] == 256 * 256 * 256) { if (bi < 2) bigs[bi++] = (const float*)d_in[k]; }
        else                                { if (si < 2) smalls[si++] = (const float*)d_in[k]; }
    }
    const float* style_resp = bigs[0];
    const float* model_resp = bigs[1];
    const float* style_map  = smalls[0];
    const float* output_map = smalls[1];

    float* pStyle = nullptr; float* pImg = nullptr;
    cudaGetSymbolAddress((void**)&pStyle, g_styleP);
    cudaGetSymbolAddress((void**)&pImg,   g_imgP);

    init_kernel<<<(NP + 255) / 256, 256>>>();
    pack_kernel<<<NP, 256>>>(style_resp, style_map, pStyle);
    pack_kernel<<<NP, 256>>>(model_resp, output_map, pImg);
    norm_kernel<<<NP, 256>>>();
    gemm_argmax_kernel<<<dim3(NP / BN, NP / BM), 256>>>();
    loss_kernel<<<N_REAL, 256>>>();
    finalize_kernel<<<1, 32>>>((float*)d_out);
}

// round 3
// speedup vs baseline: 2.5452x; 2.5452x over previous
#include <cuda_runtime.h>
#include <cuda_fp16.h>
#include <cstdint>

#define N_REAL 7225      // 85*85 patches
#define NP     7296      // padded: 57*128
#define D_REAL 2331      // 259*9
#define LD     2336      // padded K in halves (146*16)
#define NH     85
#define KSTEPS (LD / 16) // 146

#define SROW  24         // halves per smem row (16 data + 8 pad) = 48 B
#define PLANE (128 * SROW * 2)   // 6144 B per plane
#define STAGE (4 * PLANE)        // 24576 B : A_hi, A_lo, B_hi, B_lo
#define NSTAGE 4
#define SMEM_SN_BYTES 512
#define SMEM_TOTAL (SMEM_SN_BYTES + NSTAGE * STAGE)   // 98816

// ---------------- scratch (static device globals; no allocation) ------------
__device__ __half g_Ah[(size_t)NP * LD];   // style hi
__device__ __half g_Al[(size_t)NP * LD];   // style lo (residual)
__device__ __half g_Bh[(size_t)NP * LD];   // img hi
__device__ __half g_Bl[(size_t)NP * LD];   // img lo
__device__ float g_sninv[NP];
__device__ unsigned long long g_best[NP];
__device__ double g_acc;

// ---------------- helpers ----------------------------------------------------
__device__ __forceinline__ uint32_t smem_u32(const void* p) {
    uint32_t a;
    asm("{ .reg .u64 t; cvta.to.shared.u64 t, %1; cvt.u32.u64 %0, t; }" : "=r"(a) : "l"(p));
    return a;
}
__device__ __forceinline__ unsigned int encf(float f) {
    unsigned int u = __float_as_uint(f);
    unsigned int mask = (unsigned int)(-(int)(u >> 31)) | 0x80000000u;
    return u ^ mask;
}
__device__ __forceinline__ void cp16(uint32_t dst, const void* src) {
    asm volatile("cp.async.cg.shared.global [%0], [%1], 16;" :: "r"(dst), "l"(src) : "memory");
}
#define CP_COMMIT() asm volatile("cp.async.commit_group;" ::: "memory")
#define CP_WAIT2()  asm volatile("cp.async.wait_group 2;" ::: "memory")

__device__ __forceinline__ void ldsm4(uint32_t* r, uint32_t addr) {
    asm volatile("ldmatrix.sync.aligned.m8n8.x4.shared.b16 {%0,%1,%2,%3}, [%4];"
                 : "=r"(r[0]), "=r"(r[1]), "=r"(r[2]), "=r"(r[3]) : "r"(addr));
}
__device__ __forceinline__ void mma16816(float* c, const uint32_t* a, const uint32_t* b) {
    asm volatile(
        "mma.sync.aligned.m16n8k16.row.col.f32.f16.f16.f32 "
        "{%0,%1,%2,%3}, {%4,%5,%6,%7}, {%8,%9}, {%0,%1,%2,%3};"
        : "+f"(c[0]), "+f"(c[1]), "+f"(c[2]), "+f"(c[3])
        : "r"(a[0]), "r"(a[1]), "r"(a[2]), "r"(a[3]), "r"(b[0]), "r"(b[1]));
}

__device__ __forceinline__ float block_reduce_sum(float v) {
    __shared__ float sh[32];
    int lane = threadIdx.x & 31, w = threadIdx.x >> 5;
    #pragma unroll
    for (int o = 16; o; o >>= 1) v += __shfl_xor_sync(0xffffffffu, v, o);
    if (lane == 0) sh[w] = v;
    __syncthreads();
    if (w == 0) {
        v = (lane < (int)(blockDim.x >> 5)) ? sh[lane] : 0.f;
        #pragma unroll
        for (int o = 16; o; o >>= 1) v += __shfl_xor_sync(0xffffffffu, v, o);
    }
    return v;
}

// ---------------- init ------------------------------------------------------
__global__ void init_kernel() {
    int t = blockIdx.x * blockDim.x + threadIdx.x;
    if (t < NP) g_best[t] = 0ull;
    if (t == 0) g_acc = 0.0;
}

// ---------------- pack + fp16 hi/lo split -----------------------------------
__global__ void pack_kernel(const float* __restrict__ resp,
                            const float* __restrict__ map,
                            __half* __restrict__ hiDst,
                            __half* __restrict__ loDst) {
    int i = blockIdx.x;
    int ph = i / NH, pw = i - ph * NH;
    bool valid = (i < N_REAL);
    __half* hrow = hiDst + (size_t)i * LD;
    __half* lrow = loDst + (size_t)i * LD;
    for (int d = threadIdx.x; d < LD; d += blockDim.x) {
        float v = 0.f;
        if (valid && d < D_REAL) {
            int c = d / 9, rem = d - c * 9;
            int py = rem / 3, px = rem - py * 3;
            int row = ph * 3 + py, col = pw * 3 + px;
            if (c < 256) {
                v = resp[((size_t)c * 256 + row) * 256 + col];
            } else {
                int m = c - 256;
                const float* mp = map + (size_t)m * 1024 * 1024 + (size_t)(row * 4) * 1024 + col * 4;
                float s = 0.f;
                #pragma unroll
                for (int u = 0; u < 4; u++)
                    #pragma unroll
                    for (int w = 0; w < 4; w++) s += mp[u * 1024 + w];
                v = s * (50.0f / 16.0f);
            }
        }
        __half h = __float2half_rn(v);
        hrow[d] = h;
        lrow[d] = __float2half_rn(v - __half2float(h));
    }
}

// ---------------- style patch norms (hi+lo = near-exact) --------------------
__global__ void norm_kernel() {
    int j = blockIdx.x;
    const __half2* rh = (const __half2*)(g_Ah + (size_t)j * LD);
    const __half2* rl = (const __half2*)(g_Al + (size_t)j * LD);
    float s = 0.f;
    for (int t = threadIdx.x; t < LD / 2; t += blockDim.x) {
        float2 h = __half22float2(rh[t]), l = __half22float2(rl[t]);
        float x = h.x + l.x, y = h.y + l.y;
        s += x * x + y * y;
    }
    s = block_reduce_sum(s);
    if (threadIdx.x == 0) g_sninv[j] = (j < N_REAL) ? rsqrtf(s) : 0.f;
}

// ---------------- HMMA GEMM + fused argmax ----------------------------------
__device__ __forceinline__ void load_chunk(uint32_t sb, int c, int s, int i0, int j0) {
    uint32_t base = sb + s * STAGE;
    int t = threadIdx.x;
    int kc = c * 16;
    #pragma unroll
    for (int i = 0; i < 4; i++) {
        int idx = t + i * 256;
        int plane = idx >> 8;          // 0:Ah 1:Al 2:Bh 3:Bl
        int rs = idx & 255;
        int row = rs >> 1, seg = rs & 1;
        const __half* gp = (plane == 0) ? g_Ah : (plane == 1) ? g_Al
                          : (plane == 2) ? g_Bh : g_Bl;
        int grow = ((plane < 2) ? i0 : j0) + row;
        const __half* src = gp + (size_t)grow * LD + kc + seg * 8;
        uint32_t dst = base + plane * PLANE + row * 48 + seg * 16;
        cp16(dst, src);
    }
    CP_COMMIT();
}

__global__ void __launch_bounds__(256, 1)
gemm_hmma_argmax() {
    extern __shared__ char smem[];
    float* sn = (float*)smem;
    uint32_t sb = smem_u32(smem + SMEM_SN_BYTES);
    int t = threadIdx.x, lane = t & 31, w = t >> 5;
    int i0 = blockIdx.y * 128;   // style rows
    int j0 = blockIdx.x * 128;   // img rows

    if (t < 128) sn[t] = g_sninv[j0 + t];

    // prologue
    load_chunk(sb, 0, 0, i0, j0);
    load_chunk(sb, 1, 1, i0, j0);
    load_chunk(sb, 2, 2, i0, j0);

    float acc[2][8][4];
    #pragma unroll
    for (int a = 0; a < 2; a++)
        #pragma unroll
        for (int b = 0; b < 8; b++)
            #pragma unroll
            for (int q = 0; q < 4; q++) acc[a][b][q] = 0.f;

    int m0 = (w >> 1) * 32;   // warp row offset
    int n0 = (w & 1) * 64;    // warp col offset

    // per-lane ldmatrix byte offsets (within plane)
    uint32_t offA = (uint32_t)((m0 + (lane & 15)) * 48 + ((lane >> 4) << 4));
    uint32_t offB = (uint32_t)((n0 + ((lane >> 4) << 3) + (lane & 7)) * 48 +
                               (((lane >> 3) & 1) << 4));

    for (int c = 0; c < KSTEPS; c++) {
        int s = c & 3;
        uint32_t base = sb + s * STAGE;
        CP_WAIT2();
        __syncthreads();

        uint32_t ah[2][4], al[2][4], bh[8][2], bl[8][2];
        #pragma unroll
        for (int mt = 0; mt < 2; mt++) {
            uint32_t ra = base + offA + mt * (16 * 48);
            ldsm4(ah[mt], ra);
            ldsm4(al[mt], ra + PLANE);
        }
        #pragma unroll
        for (int pt = 0; pt < 4; pt++) {
            uint32_t rb = base + 2 * PLANE + offB + pt * (16 * 48);
            uint32_t r[4];
            ldsm4(r, rb);
            bh[2 * pt][0] = r[0]; bh[2 * pt][1] = r[1];
            bh[2 * pt + 1][0] = r[2]; bh[2 * pt + 1][1] = r[3];
            ldsm4(r, rb + PLANE);
            bl[2 * pt][0] = r[0]; bl[2 * pt][1] = r[1];
            bl[2 * pt + 1][0] = r[2]; bl[2 * pt + 1][1] = r[3];
        }

        if (c + 3 < KSTEPS) load_chunk(sb, c + 3, (c + 3) & 3, i0, j0);
        else CP_COMMIT();   // keep group accounting aligned

        #pragma unroll
        for (int mt = 0; mt < 2; mt++)
            #pragma unroll
            for (int nt = 0; nt < 8; nt++) {
                mma16816(acc[mt][nt], ah[mt], bh[nt]);
                mma16816(acc[mt][nt], al[mt], bh[nt]);
                mma16816(acc[mt][nt], ah[mt], bl[nt]);
            }
    }
    __syncthreads();

    // ---- epilogue: scale by sninv[j], per-row argmax, atomicMax ------------
    int qlane = lane & 3;
    #pragma unroll
    for (int mt = 0; mt < 2; mt++) {
        #pragma unroll
        for (int h = 0; h < 2; h++) {
            unsigned long long key = 0ull;
            #pragma unroll
            for (int nt = 0; nt < 8; nt++) {
                #pragma unroll
                for (int e = 0; e < 2; e++) {
                    int jc = n0 + nt * 8 + 2 * qlane + e;
                    int j = j0 + jc;
                    float v = acc[mt][nt][2 * h + e] * sn[jc];
                    if (j < N_REAL) {
                        unsigned long long k =
                            ((unsigned long long)encf(v) << 32) |
                            (unsigned long long)(0xFFFFFFFFu - (unsigned)j);
                        if (k > key) key = k;
                    }
                }
            }
            #pragma unroll
            for (int o = 1; o < 4; o <<= 1) {
                unsigned long long other = __shfl_xor_sync(0xffffffffu, key, o);
                if (other > key) key = other;
            }
            int m = i0 + m0 + mt * 16 + h * 8 + (lane >> 2);
            if (qlane == 0 && m < N_REAL) atomicMax(&g_best[m], key);
        }
    }
}

// ---------------- loss ------------------------------------------------------
__global__ void loss_kernel() {
    int i = blockIdx.x;  // img patch index
    unsigned int nearest = 0xFFFFFFFFu - (unsigned int)(g_best[i] & 0xFFFFFFFFull);
    const __half2* ih = (const __half2*)(g_Bh + (size_t)i * LD);
    const __half2* il = (const __half2*)(g_Bl + (size_t)i * LD);
    const __half2* sh2 = (const __half2*)(g_Ah + (size_t)nearest * LD);
    const __half2* sl2 = (const __half2*)(g_Al + (size_t)nearest * LD);
    float s = 0.f;
    for (int t = threadIdx.x; t < LD / 2; t += blockDim.x) {
        float2 a0 = __half22float2(ih[t]), a1 = __half22float2(il[t]);
        float2 b0 = __half22float2(sh2[t]), b1 = __half22float2(sl2[t]);
        float dx = (a0.x + a1.x) - (b0.x + b1.x);
        float dy = (a0.y + a1.y) - (b0.y + b1.y);
        s += dx * dx + dy * dy;
    }
    s = block_reduce_sum(s);
    if (threadIdx.x == 0) atomicAdd(&g_acc, (double)s);
}

__global__ void finalize_kernel(float* out) {
    if (threadIdx.x == 0)
        out[0] = (float)(g_acc / ((double)D_REAL * (double)N_REAL));
}

// ---------------- launch ----------------------------------------------------
extern "C" void kernel_launch(void* const* d_in, const int* in_sizes, int n_in,
                              void* d_out, int out_size) {
    const float* bigs[2] = {nullptr, nullptr};
    const float* smalls[2] = {nullptr, nullptr};
    int bi = 0, si = 0;
    for (int k = 0; k < n_in; k++) {
        if (in_sizes[k] == 256 * 256 * 256) { if (bi < 2) bigs[bi++] = (const float*)d_in[k]; }
        else                                { if (si < 2) smalls[si++] = (const float*)d_in[k]; }
    }
    const float* style_resp = bigs[0];
    const float* model_resp = bigs[1];
    const float* style_map  = smalls[0];
    const float* output_map = smalls[1];

    __half *pAh, *pAl, *pBh, *pBl;
    cudaGetSymbolAddress((void**)&pAh, g_Ah);
    cudaGetSymbolAddress((void**)&pAl, g_Al);
    cudaGetSymbolAddress((void**)&pBh, g_Bh);
    cudaGetSymbolAddress((void**)&pBl, g_Bl);

    cudaFuncSetAttribute(gemm_hmma_argmax,
                         cudaFuncAttributeMaxDynamicSharedMemorySize, SMEM_TOTAL);

    init_kernel<<<(NP + 255) / 256, 256>>>();
    pack_kernel<<<NP, 256>>>(style_resp, style_map, pAh, pAl);
    pack_kernel<<<NP, 256>>>(model_resp, output_map, pBh, pBl);
    norm_kernel<<<NP, 256>>>();
    gemm_hmma_argmax<<<dim3(NP / 128, NP / 128), 256, SMEM_TOTAL>>>();
    loss_kernel<<<N_REAL, 256>>>();
    finalize_kernel<<<1, 32>>>((float*)d_out);
}

// round 4
// speedup vs baseline: 3.2287x; 1.2685x over previous
#include <cuda_runtime.h>
#include <cuda_fp16.h>
#include <cstdint>

#define N_REAL 7225      // 85*85 patches
#define NP     7424      // padded: 58*128 = 29*256
#define D_REAL 2331      // 259*9
#define LD     2336      // padded K in halves (146*16)
#define NH     85
#define KCH    146       // k-chunks of 16 halves (32B)

#define BMr 128          // style rows per CTA
#define BNr 256          // img rows per CTA
#define NSTAGE 4

// stage layout (bytes)
#define AH_B 0
#define AL_B 4096
#define BH_B 8192
#define BL_B 16384
#define STAGE_B 24576

// smem map
#define FULL_OFF 0              // 4 mbarriers * 8B
#define SN_OFF   64             // 256 floats
#define TILE_OFF 2048
#define SMEM_TOTAL (TILE_OFF + NSTAGE * STAGE_B)   // 100352

// ---------------- scratch (static device globals; no allocation) ------------
// chunk-major layout: [kchunk][row][16 halves], with ldmatrix XOR swizzle baked in
__device__ __half g_Ah[(size_t)KCH * NP * 16];
__device__ __half g_Al[(size_t)KCH * NP * 16];
__device__ __half g_Bh[(size_t)KCH * NP * 16];
__device__ __half g_Bl[(size_t)KCH * NP * 16];
__device__ float g_sninv[NP];
__device__ unsigned long long g_best[NP];
__device__ double g_acc;

// ---------------- helpers ----------------------------------------------------
__device__ __forceinline__ uint32_t smem_u32(const void* p) {
    uint32_t a;
    asm("{ .reg .u64 t; cvta.to.shared.u64 t, %1; cvt.u32.u64 %0, t; }" : "=r"(a) : "l"(p));
    return a;
}
__device__ __forceinline__ unsigned int encf(float f) {
    unsigned int u = __float_as_uint(f);
    unsigned int mask = (unsigned int)(-(int)(u >> 31)) | 0x80000000u;
    return u ^ mask;
}
// position of logical half d15 (0..15) within a row's 32B chunk, row-dependent XOR
__device__ __forceinline__ int physpos(int row, int d15) {
    return ((((d15 >> 3) ^ ((row >> 2) & 1)) << 3) | (d15 & 7));
}
__device__ __forceinline__ void ldsm4(uint32_t* r, uint32_t addr) {
    asm volatile("ldmatrix.sync.aligned.m8n8.x4.shared.b16 {%0,%1,%2,%3}, [%4];"
                 : "=r"(r[0]), "=r"(r[1]), "=r"(r[2]), "=r"(r[3]) : "r"(addr));
}
__device__ __forceinline__ void mma16816(float* c, const uint32_t* a, const uint32_t* b) {
    asm volatile(
        "mma.sync.aligned.m16n8k16.row.col.f32.f16.f16.f32 "
        "{%0,%1,%2,%3}, {%4,%5,%6,%7}, {%8,%9}, {%0,%1,%2,%3};"
        : "+f"(c[0]), "+f"(c[1]), "+f"(c[2]), "+f"(c[3])
        : "r"(a[0]), "r"(a[1]), "r"(a[2]), "r"(a[3]), "r"(b[0]), "r"(b[1]));
}
__device__ __forceinline__ void mbar_init(uint32_t mbar, uint32_t count) {
    asm volatile("mbarrier.init.shared.b64 [%0], %1;" :: "r"(mbar), "r"(count) : "memory");
}
__device__ __forceinline__ void mbar_expect_tx(uint32_t mbar, uint32_t bytes) {
    asm volatile("mbarrier.arrive.expect_tx.shared.b64 _, [%0], %1;"
                 :: "r"(mbar), "r"(bytes) : "memory");
}
__device__ __forceinline__ void mbar_wait(uint32_t mbar, uint32_t phase) {
    uint32_t done;
    asm volatile(
        "{\n\t.reg .pred p;\n\t"
        "mbarrier.try_wait.parity.acquire.cta.shared::cta.b64 p, [%1], %2;\n\t"
        "selp.b32 %0, 1, 0, p;\n\t}"
        : "=r"(done) : "r"(mbar), "r"(phase) : "memory");
    while (!done) {
        asm volatile(
            "{\n\t.reg .pred p;\n\t"
            "mbarrier.try_wait.parity.acquire.cta.shared::cta.b64 p, [%1], %2, 0x989680;\n\t"
            "selp.b32 %0, 1, 0, p;\n\t}"
            : "=r"(done) : "r"(mbar), "r"(phase) : "memory");
    }
}
__device__ __forceinline__ void bulkcp(uint32_t dst, const void* src, uint32_t bytes,
                                       uint32_t mbar) {
    asm volatile(
        "cp.async.bulk.shared::cluster.global.mbarrier::complete_tx::bytes [%0], [%1], %2, [%3];"
        :: "r"(dst), "l"(src), "r"(bytes), "r"(mbar) : "memory");
}
#define FENCE_PROXY() asm volatile("fence.proxy.async.shared::cta;" ::: "memory")

__device__ __forceinline__ float block_reduce_sum(float v) {
    __shared__ float sh[32];
    int lane = threadIdx.x & 31, w = threadIdx.x >> 5;
    #pragma unroll
    for (int o = 16; o; o >>= 1) v += __shfl_xor_sync(0xffffffffu, v, o);
    if (lane == 0) sh[w] = v;
    __syncthreads();
    if (w == 0) {
        v = (lane < (int)(blockDim.x >> 5)) ? sh[lane] : 0.f;
        #pragma unroll
        for (int o = 16; o; o >>= 1) v += __shfl_xor_sync(0xffffffffu, v, o);
    }
    return v;
}

// ---------------- init ------------------------------------------------------
__global__ void init_kernel() {
    int t = blockIdx.x * blockDim.x + threadIdx.x;
    if (t < NP) g_best[t] = 0ull;
    if (t == 0) g_acc = 0.0;
}

// ---------------- pack + fp16 hi/lo split + fused norm ----------------------
__global__ void pack_kernel(const float* __restrict__ resp,
                            const float* __restrict__ map,
                            __half* __restrict__ hiDst,
                            __half* __restrict__ loDst,
                            float* __restrict__ snout) {
    int i = blockIdx.x;
    int ph = i / NH, pw = i - ph * NH;
    bool valid = (i < N_REAL);
    int par = (i >> 2) & 1;
    float ss = 0.f;
    for (int d = threadIdx.x; d < LD; d += blockDim.x) {
        float v = 0.f;
        if (valid && d < D_REAL) {
            int c = d / 9, rem = d - c * 9;
            int py = rem / 3, px = rem - py * 3;
            int row = ph * 3 + py, col = pw * 3 + px;
            if (c < 256) {
                v = resp[((size_t)c * 256 + row) * 256 + col];
            } else {
                int m = c - 256;
                const float* mp = map + (size_t)m * 1024 * 1024 + (size_t)(row * 4) * 1024 + col * 4;
                float s = 0.f;
                #pragma unroll
                for (int u = 0; u < 4; u++)
                    #pragma unroll
                    for (int w = 0; w < 4; w++) s += mp[u * 1024 + w];
                v = s * (50.0f / 16.0f);
            }
        }
        __half h = __float2half_rn(v);
        __half l = __float2half_rn(v - __half2float(h));
        int d15 = d & 15;
        size_t off = ((size_t)(d >> 4) * NP + i) * 16 +
                     ((((d15 >> 3) ^ par) << 3) | (d15 & 7));
        hiDst[off] = h;
        loDst[off] = l;
        ss += v * v;
    }
    ss = block_reduce_sum(ss);
    if (threadIdx.x == 0 && snout) snout[i] = (i < N_REAL) ? rsqrtf(ss) : 0.f;
}

// ---------------- HMMA GEMM (bulk-copy pipeline) + fused argmax -------------
__device__ __forceinline__ void issue_stage(uint32_t sb, int s, int c, int i0, int j0) {
    uint32_t full = sb + FULL_OFF + s * 8;
    uint32_t stg = sb + TILE_OFF + s * STAGE_B;
    mbar_expect_tx(full, STAGE_B);
    bulkcp(stg + AH_B, g_Ah + ((size_t)c * NP + i0) * 16, 4096, full);
    bulkcp(stg + AL_B, g_Al + ((size_t)c * NP + i0) * 16, 4096, full);
    bulkcp(stg + BH_B, g_Bh + ((size_t)c * NP + j0) * 16, 8192, full);
    bulkcp(stg + BL_B, g_Bl + ((size_t)c * NP + j0) * 16, 8192, full);
}

__global__ void __launch_bounds__(256, 1)
gemm_hmma_argmax() {
    extern __shared__ char smem[];
    uint32_t sb = smem_u32(smem);
    float* sn = (float*)(smem + SN_OFF);
    int t = threadIdx.x, lane = t & 31, w = t >> 5;
    int i0 = blockIdx.y * BMr;   // style rows
    int j0 = blockIdx.x * BNr;   // img rows

    if (t < NSTAGE) mbar_init(sb + FULL_OFF + t * 8, 1);
    sn[t] = g_sninv[j0 + t];
    __syncthreads();

    if (t == 0) {
        FENCE_PROXY();
        issue_stage(sb, 0, 0, i0, j0);
        issue_stage(sb, 1, 1, i0, j0);
        issue_stage(sb, 2, 2, i0, j0);
    }

    float acc[4][8][4];
    #pragma unroll
    for (int a = 0; a < 4; a++)
        #pragma unroll
        for (int b = 0; b < 8; b++)
            #pragma unroll
            for (int q = 0; q < 4; q++) acc[a][b][q] = 0.f;

    int m0 = (w >> 2) * 64;   // warp row offset (0/64)
    int n0 = (w & 3) * 64;    // warp col offset (0/64/128/192)

    // per-lane ldmatrix addresses (rows are 32B, XOR swizzle on 16B halves)
    uint32_t offA[4], offB[4];
    #pragma unroll
    for (int mt = 0; mt < 4; mt++) {
        int row = m0 + mt * 16 + (lane & 15);
        int seg = lane >> 4;
        offA[mt] = (uint32_t)(row * 32 + ((seg ^ ((row >> 2) & 1)) << 4));
    }
    #pragma unroll
    for (int pt = 0; pt < 4; pt++) {
        int row = pt * 16 + ((lane >> 4) << 3) + (lane & 7);
        int rr = n0 + row;
        int seg = (lane >> 3) & 1;
        offB[pt] = (uint32_t)(rr * 32 + ((seg ^ ((rr >> 2) & 1)) << 4));
    }

    int phase[NSTAGE] = {0, 0, 0, 0};
    for (int c = 0; c < KCH; c++) {
        int s = c & 3;
        uint32_t stg = sb + TILE_OFF + s * STAGE_B;
        mbar_wait(sb + FULL_OFF + s * 8, phase[s]);
        phase[s] ^= 1;

        uint32_t ah[4][4], al[4][4], bh[8][2], bl[8][2];
        #pragma unroll
        for (int mt = 0; mt < 4; mt++) {
            uint32_t a = stg + AH_B + offA[mt];
            ldsm4(ah[mt], a);
            ldsm4(al[mt], a + (AL_B - AH_B));
        }
        #pragma unroll
        for (int pt = 0; pt < 4; pt++) {
            uint32_t b = stg + BH_B + offB[pt];
            uint32_t r[4];
            ldsm4(r, b);
            bh[2 * pt][0] = r[0]; bh[2 * pt][1] = r[1];
            bh[2 * pt + 1][0] = r[2]; bh[2 * pt + 1][1] = r[3];
            ldsm4(r, b + (BL_B - BH_B));
            bl[2 * pt][0] = r[0]; bl[2 * pt][1] = r[1];
            bl[2 * pt + 1][0] = r[2]; bl[2 * pt + 1][1] = r[3];
        }
        __syncthreads();   // all warps done reading stage (c-1)&3's ldsm by now
        if (t == 0 && c + 3 < KCH) {
            FENCE_PROXY();
            issue_stage(sb, (c + 3) & 3, c + 3, i0, j0);
        }

        #pragma unroll
        for (int mt = 0; mt < 4; mt++)
            #pragma unroll
            for (int nt = 0; nt < 8; nt++) {
                mma16816(acc[mt][nt], ah[mt], bh[nt]);
                mma16816(acc[mt][nt], al[mt], bh[nt]);
                mma16816(acc[mt][nt], ah[mt], bl[nt]);
            }
    }

    // ---- epilogue: scale by sninv[j], per-row argmax, atomicMax ------------
    int qlane = lane & 3;
    #pragma unroll
    for (int mt = 0; mt < 4; mt++) {
        #pragma unroll
        for (int h = 0; h < 2; h++) {
            unsigned long long key = 0ull;
            #pragma unroll
            for (int nt = 0; nt < 8; nt++) {
                #pragma unroll
                for (int e = 0; e < 2; e++) {
                    int jc = n0 + nt * 8 + 2 * qlane + e;
                    int j = j0 + jc;
                    float v = acc[mt][nt][2 * h + e] * sn[jc];
                    if (j < N_REAL) {
                        unsigned long long k =
                            ((unsigned long long)encf(v) << 32) |
                            (unsigned long long)(0xFFFFFFFFu - (unsigned)j);
                        if (k > key) key = k;
                    }
                }
            }
            #pragma unroll
            for (int o = 1; o < 4; o <<= 1) {
                unsigned long long other = __shfl_xor_sync(0xffffffffu, key, o);
                if (other > key) key = other;
            }
            int m = i0 + m0 + mt * 16 + h * 8 + (lane >> 2);
            if (qlane == 0 && m < N_REAL) atomicMax(&g_best[m], key);
        }
    }
}

// ---------------- loss ------------------------------------------------------
__global__ void loss_kernel() {
    int i = blockIdx.x;  // img patch index
    unsigned int nearest = 0xFFFFFFFFu - (unsigned int)(g_best[i] & 0xFFFFFFFFull);
    int pi = (i >> 2) & 1, pn = ((int)nearest >> 2) & 1;
    float s = 0.f;
    for (int g = threadIdx.x; g < LD / 8; g += blockDim.x) {  // 292 8-half groups
        int c = g >> 1, seg = g & 1;
        size_t io = ((size_t)c * NP + i) * 16 + (size_t)((seg ^ pi) << 3);
        size_t so = ((size_t)c * NP + nearest) * 16 + (size_t)((seg ^ pn) << 3);
        const __half2* ih = (const __half2*)(g_Bh + io);
        const __half2* il = (const __half2*)(g_Bl + io);
        const __half2* sh2 = (const __half2*)(g_Ah + so);
        const __half2* sl2 = (const __half2*)(g_Al + so);
        #pragma unroll
        for (int q = 0; q < 4; q++) {
            float2 a0 = __half22float2(ih[q]), a1 = __half22float2(il[q]);
            float2 b0 = __half22float2(sh2[q]), b1 = __half22float2(sl2[q]);
            float dx = (a0.x + a1.x) - (b0.x + b1.x);
            float dy = (a0.y + a1.y) - (b0.y + b1.y);
            s += dx * dx + dy * dy;
        }
    }
    s = block_reduce_sum(s);
    if (threadIdx.x == 0) atomicAdd(&g_acc, (double)s);
}

__global__ void finalize_kernel(float* out) {
    if (threadIdx.x == 0)
        out[0] = (float)(g_acc / ((double)D_REAL * (double)N_REAL));
}

// ---------------- launch ----------------------------------------------------
extern "C" void kernel_launch(void* const* d_in, const int* in_sizes, int n_in,
                              void* d_out, int out_size) {
    const float* bigs[2] = {nullptr, nullptr};
    const float* smalls[2] = {nullptr, nullptr};
    int bi = 0, si = 0;
    for (int k = 0; k < n_in; k++) {
        if (in_sizes[k] == 256 * 256 * 256) { if (bi < 2) bigs[bi++] = (const float*)d_in[k]; }
        else                                { if (si < 2) smalls[si++] = (const float*)d_in[k]; }
    }
    const float* style_resp = bigs[0];
    const float* model_resp = bigs[1];
    const float* style_map  = smalls[0];
    const float* output_map = smalls[1];

    __half *pAh, *pAl, *pBh, *pBl;
    float* pSn;
    cudaGetSymbolAddress((void**)&pAh, g_Ah);
    cudaGetSymbolAddress((void**)&pAl, g_Al);
    cudaGetSymbolAddress((void**)&pBh, g_Bh);
    cudaGetSymbolAddress((void**)&pBl, g_Bl);
    cudaGetSymbolAddress((void**)&pSn, g_sninv);

    cudaFuncSetAttribute(gemm_hmma_argmax,
                         cudaFuncAttributeMaxDynamicSharedMemorySize, SMEM_TOTAL);

    init_kernel<<<(NP + 255) / 256, 256>>>();
    pack_kernel<<<NP, 256>>>(style_resp, style_map, pAh, pAl, pSn);      // style (+norms)
    pack_kernel<<<NP, 256>>>(model_resp, output_map, pBh, pBl, nullptr); // img
    gemm_hmma_argmax<<<dim3(NP / BNr, NP / BMr), 256, SMEM_TOTAL>>>();
    loss_kernel<<<N_REAL, 256>>>();
    finalize_kernel<<<1, 32>>>((float*)d_out);
}

// round 7
// speedup vs baseline: 7.6754x; 2.3772x over previous
#include <cuda_runtime.h>
#include <cuda_fp16.h>
#include <cstdint>

#define N_REAL 7225      // 85*85 patches
#define NP     7424      // padded: 58*128 = 29*256
#define D_REAL 2331      // 259*9
#define KCH    148       // k-chunks of 16 halves (32B); 37 stages of 4
#define LD     (KCH * 16) // 2368 halves
#define NH     85

#define BMr 128          // style rows per CTA
#define BNr 256          // img rows per CTA
#define NSTAGE 3
#define CPS 4            // chunks per stage

// per-chunk layout inside a stage: Ah (4KB) then Bh (8KB)
#define CHUNK_B 12288
#define STAGE_B (CPS * CHUNK_B)          // 49152

// smem map
#define FULL_OFF 0                        // 3 mbarriers * 8B
#define SN_OFF   64                       // 256 floats
#define TILE_OFF 2048
#define SMEM_TOTAL (TILE_OFF + NSTAGE * STAGE_B)   // 149504

// ---------------- scratch (static device globals; no allocation) ------------
// chunk-major layout: [kchunk][row][16 halves], ldmatrix XOR swizzle baked in
__device__ __half g_Ah[(size_t)KCH * NP * 16];   // style hi  (GEMM + loss)
__device__ __half g_Al[(size_t)KCH * NP * 16];   // style lo  (loss only)
__device__ __half g_Bh[(size_t)KCH * NP * 16];   // img hi    (GEMM + loss)
__device__ __half g_Bl[(size_t)KCH * NP * 16];   // img lo    (loss only)
__device__ float g_sninv[NP];
__device__ unsigned long long g_best[NP];
__device__ double g_acc;

// ---------------- helpers ----------------------------------------------------
__device__ __forceinline__ uint32_t smem_u32(const void* p) {
    uint32_t a;
    asm("{ .reg .u64 t; cvta.to.shared.u64 t, %1; cvt.u32.u64 %0, t; }" : "=r"(a) : "l"(p));
    return a;
}
__device__ __forceinline__ unsigned int encf(float f) {
    unsigned int u = __float_as_uint(f);
    unsigned int mask = (unsigned int)(-(int)(u >> 31)) | 0x80000000u;
    return u ^ mask;
}
__device__ __forceinline__ void ldsm4(uint32_t* r, uint32_t addr) {
    asm volatile("ldmatrix.sync.aligned.m8n8.x4.shared.b16 {%0,%1,%2,%3}, [%4];"
                 : "=r"(r[0]), "=r"(r[1]), "=r"(r[2]), "=r"(r[3]) : "r"(addr));
}
__device__ __forceinline__ void mma16816(float* c, const uint32_t* a, const uint32_t* b) {
    asm volatile(
        "mma.sync.aligned.m16n8k16.row.col.f32.f16.f16.f32 "
        "{%0,%1,%2,%3}, {%4,%5,%6,%7}, {%8,%9}, {%0,%1,%2,%3};"
        : "+f"(c[0]), "+f"(c[1]), "+f"(c[2]), "+f"(c[3])
        : "r"(a[0]), "r"(a[1]), "r"(a[2]), "r"(a[3]), "r"(b[0]), "r"(b[1]));
}
__device__ __forceinline__ void mbar_init(uint32_t mbar, uint32_t count) {
    asm volatile("mbarrier.init.shared.b64 [%0], %1;" :: "r"(mbar), "r"(count) : "memory");
}
__device__ __forceinline__ void mbar_expect_tx(uint32_t mbar, uint32_t bytes) {
    asm volatile("mbarrier.arrive.expect_tx.shared.b64 _, [%0], %1;"
                 :: "r"(mbar), "r"(bytes) : "memory");
}
__device__ __forceinline__ void mbar_wait(uint32_t mbar, uint32_t phase) {
    uint32_t done;
    asm volatile(
        "{\n\t.reg .pred p;\n\t"
        "mbarrier.try_wait.parity.acquire.cta.shared::cta.b64 p, [%1], %2;\n\t"
        "selp.b32 %0, 1, 0, p;\n\t}"
        : "=r"(done) : "r"(mbar), "r"(phase) : "memory");
    while (!done) {
        asm volatile(
            "{\n\t.reg .pred p;\n\t"
            "mbarrier.try_wait.parity.acquire.cta.shared::cta.b64 p, [%1], %2, 0x989680;\n\t"
            "selp.b32 %0, 1, 0, p;\n\t}"
            : "=r"(done) : "r"(mbar), "r"(phase) : "memory");
    }
}
__device__ __forceinline__ void bulkcp(uint32_t dst, const void* src, uint32_t bytes,
                                       uint32_t mbar) {
    asm volatile(
        "cp.async.bulk.shared::cluster.global.mbarrier::complete_tx::bytes [%0], [%1], %2, [%3];"
        :: "r"(dst), "l"(src), "r"(bytes), "r"(mbar) : "memory");
}
#define FENCE_PROXY() asm volatile("fence.proxy.async.shared::cta;" ::: "memory")

__device__ __forceinline__ float block_reduce_sum(float v) {
    __shared__ float sh[32];
    int lane = threadIdx.x & 31, w = threadIdx.x >> 5;
    #pragma unroll
    for (int o = 16; o; o >>= 1) v += __shfl_xor_sync(0xffffffffu, v, o);
    if (lane == 0) sh[w] = v;
    __syncthreads();
    if (w == 0) {
        v = (lane < (int)(blockDim.x >> 5)) ? sh[lane] : 0.f;
        #pragma unroll
        for (int o = 16; o; o >>= 1) v += __shfl_xor_sync(0xffffffffu, v, o);
    }
    return v;
}

// ---------------- init ------------------------------------------------------
__global__ void init_kernel() {
    int t = blockIdx.x * blockDim.x + threadIdx.x;
    if (t < NP) g_best[t] = 0ull;
    if (t == 0) g_acc = 0.0;
}

// ---------------- pack + fp16 hi/lo split + fused norm ----------------------
__global__ void pack_kernel(const float* __restrict__ resp,
                            const float* __restrict__ map,
                            __half* __restrict__ hiDst,
                            __half* __restrict__ loDst,
                            float* __restrict__ snout) {
    int i = blockIdx.x;
    int ph = i / NH, pw = i - ph * NH;
    bool valid = (i < N_REAL);
    int par = (i >> 2) & 1;
    float ss = 0.f;
    for (int d = threadIdx.x; d < LD; d += blockDim.x) {
        float v = 0.f;
        if (valid && d < D_REAL) {
            int c = d / 9, rem = d - c * 9;
            int py = rem / 3, px = rem - py * 3;
            int row = ph * 3 + py, col = pw * 3 + px;
            if (c < 256) {
                v = resp[((size_t)c * 256 + row) * 256 + col];
            } else {
                int m = c - 256;
                const float* mp = map + (size_t)m * 1024 * 1024 + (size_t)(row * 4) * 1024 + col * 4;
                float s = 0.f;
                #pragma unroll
                for (int u = 0; u < 4; u++)
                    #pragma unroll
                    for (int w = 0; w < 4; w++) s += mp[u * 1024 + w];
                v = s * (50.0f / 16.0f);
            }
        }
        __half h = __float2half_rn(v);
        __half l = __float2half_rn(v - __half2float(h));
        int d15 = d & 15;
        size_t off = ((size_t)(d >> 4) * NP + i) * 16 +
                     ((((d15 >> 3) ^ par) << 3) | (d15 & 7));
        hiDst[off] = h;
        loDst[off] = l;
        ss += v * v;
    }
    ss = block_reduce_sum(ss);
    if (threadIdx.x == 0 && snout) snout[i] = (i < N_REAL) ? rsqrtf(ss) : 0.f;
}

// ---------------- HMMA GEMM (hi-only, bulk-copy pipeline) + fused argmax ----
__device__ __forceinline__ void issue_stage(uint32_t sb, int s, int st, int i0, int j0) {
    uint32_t full = sb + FULL_OFF + s * 8;
    uint32_t stg = sb + TILE_OFF + s * STAGE_B;
    mbar_expect_tx(full, STAGE_B);
    #pragma unroll
    for (int q = 0; q < CPS; q++) {
        int c = st * CPS + q;
        bulkcp(stg + q * CHUNK_B,        g_Ah + ((size_t)c * NP + i0) * 16, 4096, full);
        bulkcp(stg + q * CHUNK_B + 4096, g_Bh + ((size_t)c * NP + j0) * 16, 8192, full);
    }
}

__global__ void __launch_bounds__(256, 1)
gemm_hmma_argmax() {
    extern __shared__ char smem[];
    uint32_t sb = smem_u32(smem);
    float* sn = (float*)(smem + SN_OFF);
    int t = threadIdx.x, lane = t & 31, w = t >> 5;
    int i0 = blockIdx.y * BMr;   // style rows
    int j0 = blockIdx.x * BNr;   // img rows

    if (t < NSTAGE) mbar_init(sb + FULL_OFF + t * 8, 1);
    sn[t] = g_sninv[j0 + t];
    __syncthreads();

    if (t == 0) {
        FENCE_PROXY();
        issue_stage(sb, 0, 0, i0, j0);
        issue_stage(sb, 1, 1, i0, j0);
    }

    float acc[4][8][4];
    #pragma unroll
    for (int a = 0; a < 4; a++)
        #pragma unroll
        for (int b = 0; b < 8; b++)
            #pragma unroll
            for (int q = 0; q < 4; q++) acc[a][b][q] = 0.f;

    int m0 = (w >> 2) * 64;   // warp row offset (0/64)
    int n0 = (w & 3) * 64;    // warp col offset (0/64/128/192)

    // per-lane ldmatrix byte offsets inside a chunk's A/B plane
    uint32_t offA[4], offB[4];
    #pragma unroll
    for (int mt = 0; mt < 4; mt++) {
        int row = m0 + mt * 16 + (lane & 15);
        int seg = lane >> 4;
        offA[mt] = (uint32_t)(row * 32 + ((seg ^ ((row >> 2) & 1)) << 4));
    }
    #pragma unroll
    for (int pt = 0; pt < 4; pt++) {
        int rr = n0 + pt * 16 + ((lane >> 4) << 3) + (lane & 7);
        int seg = (lane >> 3) & 1;
        offB[pt] = (uint32_t)(rr * 32 + ((seg ^ ((rr >> 2) & 1)) << 4));
    }

    int phase[NSTAGE] = {0, 0, 0};
    const int NST = KCH / CPS;   // 37
    for (int st = 0; st < NST; st++) {
        int s = st % NSTAGE;
        uint32_t stg = sb + TILE_OFF + s * STAGE_B;
        mbar_wait(sb + FULL_OFF + s * 8, phase[s]);
        phase[s] ^= 1;

        #pragma unroll
        for (int q = 0; q < CPS; q++) {
            uint32_t cb = stg + q * CHUNK_B;
            uint32_t ah[4][4], bh[8][2];
            #pragma unroll
            for (int mt = 0; mt < 4; mt++) ldsm4(ah[mt], cb + offA[mt]);
            #pragma unroll
            for (int pt = 0; pt < 4; pt++) {
                uint32_t r[4];
                ldsm4(r, cb + 4096 + offB[pt]);
                bh[2 * pt][0] = r[0]; bh[2 * pt][1] = r[1];
                bh[2 * pt + 1][0] = r[2]; bh[2 * pt + 1][1] = r[3];
            }
            if (q == CPS - 1) {
                __syncthreads();   // all warps done reading this stage
                if (t == 0 && st + 2 < NST) {
                    FENCE_PROXY();
                    issue_stage(sb, (st + 2) % NSTAGE, st + 2, i0, j0);
                }
            }
            #pragma unroll
            for (int mt = 0; mt < 4; mt++)
                #pragma unroll
                for (int nt = 0; nt < 8; nt++)
                    mma16816(acc[mt][nt], ah[mt], bh[nt]);
        }
    }

    // ---- epilogue: scale by sninv[j], per-row argmax, atomicMax ------------
    int qlane = lane & 3;
    #pragma unroll
    for (int mt = 0; mt < 4; mt++) {
        #pragma unroll
        for (int h = 0; h < 2; h++) {
            unsigned long long key = 0ull;
            #pragma unroll
            for (int nt = 0; nt < 8; nt++) {
                #pragma unroll
                for (int e = 0; e < 2; e++) {
                    int jc = n0 + nt * 8 + 2 * qlane + e;
                    int j = j0 + jc;
                    float v = acc[mt][nt][2 * h + e] * sn[jc];
                    if (j < N_REAL) {
                        unsigned long long k =
                            ((unsigned long long)encf(v) << 32) |
                            (unsigned long long)(0xFFFFFFFFu - (unsigned)j);
                        if (k > key) key = k;
                    }
                }
            }
            #pragma unroll
            for (int o = 1; o < 4; o <<= 1) {
                unsigned long long other = __shfl_xor_sync(0xffffffffu, key, o);
                if (other > key) key = other;
            }
            int m = i0 + m0 + mt * 16 + h * 8 + (lane >> 2);
            if (qlane == 0 && m < N_REAL) atomicMax(&g_best[m], key);
        }
    }
}

// ---------------- loss (exact hi+lo values) ---------------------------------
__global__ void loss_kernel() {
    int i = blockIdx.x;  // img patch index
    unsigned int nearest = 0xFFFFFFFFu - (unsigned int)(g_best[i] & 0xFFFFFFFFull);
    int pi = (i >> 2) & 1, pn = ((int)nearest >> 2) & 1;
    float s = 0.f;
    for (int g = threadIdx.x; g < LD / 8; g += blockDim.x) {
        int c = g >> 1, seg = g & 1;
        size_t io = ((size_t)c * NP + i) * 16 + (size_t)((seg ^ pi) << 3);
        size_t so = ((size_t)c * NP + nearest) * 16 + (size_t)((seg ^ pn) << 3);
        const __half2* ih = (const __half2*)(g_Bh + io);
        const __half2* il = (const __half2*)(g_Bl + io);
        const __half2* sh2 = (const __half2*)(g_Ah + so);
        const __half2* sl2 = (const __half2*)(g_Al + so);
        #pragma unroll
        for (int q = 0; q < 4; q++) {
            float2 a0 = __half22float2(ih[q]), a1 = __half22float2(il[q]);
            float2 b0 = __half22float2(sh2[q]), b1 = __half22float2(sl2[q]);
            float dx = (a0.x + a1.x) - (b0.x + b1.x);
            float dy = (a0.y + a1.y) - (b0.y + b1.y);
            s += dx * dx + dy * dy;
        }
    }
    s = block_reduce_sum(s);
    if (threadIdx.x == 0) atomicAdd(&g_acc, (double)s);
}

__global__ void finalize_kernel(float* out) {
    if (threadIdx.x == 0)
        out[0] = (float)(g_acc / ((double)D_REAL * (double)N_REAL));
}

// ---------------- launch ----------------------------------------------------
extern "C" void kernel_launch(void* const* d_in, const int* in_sizes, int n_in,
                              void* d_out, int out_size) {
    const float* bigs[2] = {nullptr, nullptr};
    const float* smalls[2] = {nullptr, nullptr};
    int bi = 0, si = 0;
    for (int k = 0; k < n_in; k++) {
        if (in_sizes[k] == 256 * 256 * 256) { if (bi < 2) bigs[bi++] = (const float*)d_in[k]; }
        else                                { if (si < 2) smalls[si++] = (const float*)d_in[k]; }
    }
    const float* style_resp = bigs[0];
    const float* model_resp = bigs[1];
    const float* style_map  = smalls[0];
    const float* output_map = smalls[1];

    __half *pAh, *pAl, *pBh, *pBl;
    float* pSn;
    cudaGetSymbolAddress((void**)&pAh, g_Ah);
    cudaGetSymbolAddress((void**)&pAl, g_Al);
    cudaGetSymbolAddress((void**)&pBh, g_Bh);
    cudaGetSymbolAddress((void**)&pBl, g_Bl);
    cudaGetSymbolAddress((void**)&pSn, g_sninv);

    cudaFuncSetAttribute(gemm_hmma_argmax,
                         cudaFuncAttributeMaxDynamicSharedMemorySize, SMEM_TOTAL);

    init_kernel<<<(NP + 255) / 256, 256>>>();
    pack_kernel<<<NP, 256>>>(style_resp, style_map, pAh, pAl, pSn);      // style (+norms)
    pack_kernel<<<NP, 256>>>(model_resp, output_map, pBh, pBl, nullptr); // img
    gemm_hmma_argmax<<<dim3(NP / BNr, NP / BMr), 256, SMEM_TOTAL>>>();
    loss_kernel<<<N_REAL, 256>>>();
    finalize_kernel<<<1, 32>>>((float*)d_out);
}

// round 8
// speedup vs baseline: 7.7451x; 1.0091x over previous
#include <cuda_runtime.h>
#include <cuda_fp16.h>
#include <cstdint>

#define N_REAL 7225      // 85*85 patches
#define NP     7424      // padded: 58*128 = 29*256
#define D_REAL 2331      // 259*9
#define KCH    144       // k-chunks of 16 halves (32B); 18 stages of 8
#define LD     (KCH * 16) // 2304 halves >= 2331? NO -- need >= D_REAL/… see below
#define NH     85

// NOTE: KCH must cover D_REAL=2331 halves -> ceil(2331/16)=146 -> pad to 152 (19*8)
#undef KCH
#undef LD
#define KCH    152
#define LD     (KCH * 16)   // 2432

#define BMr 128          // style rows per CTA
#define BNr 256          // img rows per CTA
#define NSTAGE 2
#define CPS 8            // chunks per stage

// per-chunk layout inside a stage: Ah (4KB) then Bh (8KB)
#define CHUNK_B 12288
#define STAGE_B (CPS * CHUNK_B)          // 98304

// smem map
#define FULL_OFF 0                        // 2 mbarriers * 8B
#define SN_OFF   64                       // 256 floats
#define TILE_OFF 2048
#define SMEM_TOTAL (TILE_OFF + NSTAGE * STAGE_B)   // 198656

// ---------------- scratch (static device globals; no allocation) ------------
// chunk-major layout: [kchunk][row][16 halves], ldmatrix XOR swizzle baked in
__device__ __half g_Ah[(size_t)KCH * NP * 16];   // style hi  (GEMM + loss)
__device__ __half g_Al[(size_t)KCH * NP * 16];   // style lo  (loss only)
__device__ __half g_Bh[(size_t)KCH * NP * 16];   // img hi    (GEMM + loss)
__device__ __half g_Bl[(size_t)KCH * NP * 16];   // img lo    (loss only)
__device__ float g_sninv[NP];
__device__ unsigned long long g_best[NP];
__device__ double g_acc;

// ---------------- helpers ----------------------------------------------------
__device__ __forceinline__ uint32_t smem_u32(const void* p) {
    uint32_t a;
    asm("{ .reg .u64 t; cvta.to.shared.u64 t, %1; cvt.u32.u64 %0, t; }" : "=r"(a) : "l"(p));
    return a;
}
__device__ __forceinline__ unsigned int encf(float f) {
    unsigned int u = __float_as_uint(f);
    unsigned int mask = (unsigned int)(-(int)(u >> 31)) | 0x80000000u;
    return u ^ mask;
}
__device__ __forceinline__ void ldsm4(uint32_t* r, uint32_t addr) {
    asm volatile("ldmatrix.sync.aligned.m8n8.x4.shared.b16 {%0,%1,%2,%3}, [%4];"
                 : "=r"(r[0]), "=r"(r[1]), "=r"(r[2]), "=r"(r[3]) : "r"(addr));
}
__device__ __forceinline__ void mma16816(float* c, const uint32_t* a, const uint32_t* b) {
    asm volatile(
        "mma.sync.aligned.m16n8k16.row.col.f32.f16.f16.f32 "
        "{%0,%1,%2,%3}, {%4,%5,%6,%7}, {%8,%9}, {%0,%1,%2,%3};"
        : "+f"(c[0]), "+f"(c[1]), "+f"(c[2]), "+f"(c[3])
        : "r"(a[0]), "r"(a[1]), "r"(a[2]), "r"(a[3]), "r"(b[0]), "r"(b[1]));
}
__device__ __forceinline__ void mbar_init(uint32_t mbar, uint32_t count) {
    asm volatile("mbarrier.init.shared.b64 [%0], %1;" :: "r"(mbar), "r"(count) : "memory");
}
__device__ __forceinline__ void mbar_expect_tx(uint32_t mbar, uint32_t bytes) {
    asm volatile("mbarrier.arrive.expect_tx.shared.b64 _, [%0], %1;"
                 :: "r"(mbar), "r"(bytes) : "memory");
}
__device__ __forceinline__ void mbar_wait(uint32_t mbar, uint32_t phase) {
    uint32_t done;
    asm volatile(
        "{\n\t.reg .pred p;\n\t"
        "mbarrier.try_wait.parity.acquire.cta.shared::cta.b64 p, [%1], %2;\n\t"
        "selp.b32 %0, 1, 0, p;\n\t}"
        : "=r"(done) : "r"(mbar), "r"(phase) : "memory");
    while (!done) {
        asm volatile(
            "{\n\t.reg .pred p;\n\t"
            "mbarrier.try_wait.parity.acquire.cta.shared::cta.b64 p, [%1], %2, 0x989680;\n\t"
            "selp.b32 %0, 1, 0, p;\n\t}"
            : "=r"(done) : "r"(mbar), "r"(phase) : "memory");
    }
}
__device__ __forceinline__ void bulkcp(uint32_t dst, const void* src, uint32_t bytes,
                                       uint32_t mbar) {
    asm volatile(
        "cp.async.bulk.shared::cluster.global.mbarrier::complete_tx::bytes [%0], [%1], %2, [%3];"
        :: "r"(dst), "l"(src), "r"(bytes), "r"(mbar) : "memory");
}
#define FENCE_PROXY() asm volatile("fence.proxy.async.shared::cta;" ::: "memory")

__device__ __forceinline__ float block_reduce_sum(float v) {
    __shared__ float sh[32];
    int lane = threadIdx.x & 31, w = threadIdx.x >> 5;
    #pragma unroll
    for (int o = 16; o; o >>= 1) v += __shfl_xor_sync(0xffffffffu, v, o);
    if (lane == 0) sh[w] = v;
    __syncthreads();
    if (w == 0) {
        v = (lane < (int)(blockDim.x >> 5)) ? sh[lane] : 0.f;
        #pragma unroll
        for (int o = 16; o; o >>= 1) v += __shfl_xor_sync(0xffffffffu, v, o);
    }
    return v;
}

// ---------------- init ------------------------------------------------------
__global__ void init_kernel() {
    int t = blockIdx.x * blockDim.x + threadIdx.x;
    if (t < NP) g_best[t] = 0ull;
    if (t == 0) g_acc = 0.0;
}

// ---------------- pack + fp16 hi/lo split + fused norm ----------------------
__global__ void pack_kernel(const float* __restrict__ resp,
                            const float* __restrict__ map,
                            __half* __restrict__ hiDst,
                            __half* __restrict__ loDst,
                            float* __restrict__ snout) {
    int i = blockIdx.x;
    int ph = i / NH, pw = i - ph * NH;
    bool valid = (i < N_REAL);
    int par = (i >> 2) & 1;
    float ss = 0.f;
    for (int d = threadIdx.x; d < LD; d += blockDim.x) {
        float v = 0.f;
        if (valid && d < D_REAL) {
            int c = d / 9, rem = d - c * 9;
            int py = rem / 3, px = rem - py * 3;
            int row = ph * 3 + py, col = pw * 3 + px;
            if (c < 256) {
                v = resp[((size_t)c * 256 + row) * 256 + col];
            } else {
                int m = c - 256;
                const float* mp = map + (size_t)m * 1024 * 1024 + (size_t)(row * 4) * 1024 + col * 4;
                float s = 0.f;
                #pragma unroll
                for (int u = 0; u < 4; u++)
                    #pragma unroll
                    for (int w = 0; w < 4; w++) s += mp[u * 1024 + w];
                v = s * (50.0f / 16.0f);
            }
        }
        __half h = __float2half_rn(v);
        __half l = __float2half_rn(v - __half2float(h));
        int d15 = d & 15;
        size_t off = ((size_t)(d >> 4) * NP + i) * 16 +
                     ((((d15 >> 3) ^ par) << 3) | (d15 & 7));
        hiDst[off] = h;
        loDst[off] = l;
        ss += v * v;
    }
    ss = block_reduce_sum(ss);
    if (threadIdx.x == 0 && snout) snout[i] = (i < N_REAL) ? rsqrtf(ss) : 0.f;
}

// ---------------- HMMA GEMM (hi-only, pipelined frags) + fused argmax -------
__device__ __forceinline__ void issue_stage(uint32_t sb, int s, int st, int i0, int j0) {
    uint32_t full = sb + FULL_OFF + s * 8;
    uint32_t stg = sb + TILE_OFF + s * STAGE_B;
    mbar_expect_tx(full, STAGE_B);
    #pragma unroll
    for (int q = 0; q < CPS; q++) {
        int c = st * CPS + q;
        bulkcp(stg + q * CHUNK_B,        g_Ah + ((size_t)c * NP + i0) * 16, 4096, full);
        bulkcp(stg + q * CHUNK_B + 4096, g_Bh + ((size_t)c * NP + j0) * 16, 8192, full);
    }
}

struct Frag {
    uint32_t a[4][4];
    uint32_t b[8][2];
};
__device__ __forceinline__ void load_frags(Frag& f, uint32_t cb,
                                           const uint32_t* offA, const uint32_t* offB) {
    #pragma unroll
    for (int mt = 0; mt < 4; mt++) ldsm4(f.a[mt], cb + offA[mt]);
    #pragma unroll
    for (int pt = 0; pt < 4; pt++) {
        uint32_t r[4];
        ldsm4(r, cb + 4096 + offB[pt]);
        f.b[2 * pt][0] = r[0]; f.b[2 * pt][1] = r[1];
        f.b[2 * pt + 1][0] = r[2]; f.b[2 * pt + 1][1] = r[3];
    }
}

__global__ void __launch_bounds__(256, 1)
gemm_hmma_argmax() {
    extern __shared__ char smem[];
    uint32_t sb = smem_u32(smem);
    float* sn = (float*)(smem + SN_OFF);
    int t = threadIdx.x, lane = t & 31, w = t >> 5;
    int i0 = blockIdx.y * BMr;   // style rows
    int j0 = blockIdx.x * BNr;   // img rows

    if (t < NSTAGE) mbar_init(sb + FULL_OFF + t * 8, 1);
    sn[t] = g_sninv[j0 + t];
    __syncthreads();

    if (t == 0) {
        FENCE_PROXY();
        issue_stage(sb, 0, 0, i0, j0);
        issue_stage(sb, 1, 1, i0, j0);
    }

    float acc[4][8][4];
    #pragma unroll
    for (int a = 0; a < 4; a++)
        #pragma unroll
        for (int b = 0; b < 8; b++)
            #pragma unroll
            for (int q = 0; q < 4; q++) acc[a][b][q] = 0.f;

    int m0 = (w >> 2) * 64;   // warp row offset (0/64)
    int n0 = (w & 3) * 64;    // warp col offset (0/64/128/192)

    uint32_t offA[4], offB[4];
    #pragma unroll
    for (int mt = 0; mt < 4; mt++) {
        int row = m0 + mt * 16 + (lane & 15);
        int seg = lane >> 4;
        offA[mt] = (uint32_t)(row * 32 + ((seg ^ ((row >> 2) & 1)) << 4));
    }
    #pragma unroll
    for (int pt = 0; pt < 4; pt++) {
        int rr = n0 + pt * 16 + ((lane >> 4) << 3) + (lane & 7);
        int seg = (lane >> 3) & 1;
        offB[pt] = (uint32_t)(rr * 32 + ((seg ^ ((rr >> 2) & 1)) << 4));
    }

    Frag frag[2];
    int phase[NSTAGE] = {0, 0};
    const int NST = KCH / CPS;   // 19

    // prologue: wait stage0, load chunk0 fragments
    mbar_wait(sb + FULL_OFF + 0, 0);
    phase[0] ^= 1;
    load_frags(frag[0], sb + TILE_OFF + 0, offA, offB);

    int cur = 0;
    for (int st = 0; st < NST; st++) {
        int s = st & 1;
        uint32_t stg = sb + TILE_OFF + s * STAGE_B;
        #pragma unroll
        for (int q = 0; q < CPS; q++) {
            bool lastAll = (st == NST - 1) && (q == CPS - 1);
            if (!lastAll) {
                if (q < CPS - 1) {
                    load_frags(frag[cur ^ 1], stg + (q + 1) * CHUNK_B, offA, offB);
                } else {
                    int ns = (st + 1) & 1;
                    mbar_wait(sb + FULL_OFF + ns * 8, phase[ns]);
                    phase[ns] ^= 1;
                    load_frags(frag[cur ^ 1], sb + TILE_OFF + ns * STAGE_B, offA, offB);
                }
            }
            if (q == CPS - 1) {
                __syncthreads();   // all warps done with ldsm from stage s
                if (t == 0 && st + 2 < NST) {
                    FENCE_PROXY();
                    issue_stage(sb, s, st + 2, i0, j0);
                }
            }
            #pragma unroll
            for (int mt = 0; mt < 4; mt++)
                #pragma unroll
                for (int nt = 0; nt < 8; nt++)
                    mma16816(acc[mt][nt], frag[cur].a[mt], frag[cur].b[nt]);
            cur ^= 1;
        }
    }

    // ---- epilogue: scale by sninv[j], per-row argmax, atomicMax ------------
    int qlane = lane & 3;
    #pragma unroll
    for (int mt = 0; mt < 4; mt++) {
        #pragma unroll
        for (int h = 0; h < 2; h++) {
            unsigned long long key = 0ull;
            #pragma unroll
            for (int nt = 0; nt < 8; nt++) {
                #pragma unroll
                for (int e = 0; e < 2; e++) {
                    int jc = n0 + nt * 8 + 2 * qlane + e;
                    int j = j0 + jc;
                    float v = acc[mt][nt][2 * h + e] * sn[jc];
                    if (j < N_REAL) {
                        unsigned long long k =
                            ((unsigned long long)encf(v) << 32) |
                            (unsigned long long)(0xFFFFFFFFu - (unsigned)j);
                        if (k > key) key = k;
                    }
                }
            }
            #pragma unroll
            for (int o = 1; o < 4; o <<= 1) {
                unsigned long long other = __shfl_xor_sync(0xffffffffu, key, o);
                if (other > key) key = other;
            }
            int m = i0 + m0 + mt * 16 + h * 8 + (lane >> 2);
            if (qlane == 0 && m < N_REAL) atomicMax(&g_best[m], key);
        }
    }
}

// ---------------- loss (exact hi+lo values) ---------------------------------
__global__ void loss_kernel() {
    int i = blockIdx.x;  // img patch index
    unsigned int nearest = 0xFFFFFFFFu - (unsigned int)(g_best[i] & 0xFFFFFFFFull);
    int pi = (i >> 2) & 1, pn = ((int)nearest >> 2) & 1;
    float s = 0.f;
    for (int g = threadIdx.x; g < LD / 8; g += blockDim.x) {
        int c = g >> 1, seg = g & 1;
        size_t io = ((size_t)c * NP + i) * 16 + (size_t)((seg ^ pi) << 3);
        size_t so = ((size_t)c * NP + nearest) * 16 + (size_t)((seg ^ pn) << 3);
        const __half2* ih = (const __half2*)(g_Bh + io);
        const __half2* il = (const __half2*)(g_Bl + io);
        const __half2* sh2 = (const __half2*)(g_Ah + so);
        const __half2* sl2 = (const __half2*)(g_Al + so);
        #pragma unroll
        for (int q = 0; q < 4; q++) {
            float2 a0 = __half22float2(ih[q]), a1 = __half22float2(il[q]);
            float2 b0 = __half22float2(sh2[q]), b1 = __half22float2(sl2[q]);
            float dx = (a0.x + a1.x) - (b0.x + b1.x);
            float dy = (a0.y + a1.y) - (b0.y + b1.y);
            s += dx * dx + dy * dy;
        }
    }
    s = block_reduce_sum(s);
    if (threadIdx.x == 0) atomicAdd(&g_acc, (double)s);
}

__global__ void finalize_kernel(float* out) {
    if (threadIdx.x == 0)
        out[0] = (float)(g_acc / ((double)D_REAL * (double)N_REAL));
}

// ---------------- launch ----------------------------------------------------
extern "C" void kernel_launch(void* const* d_in, const int* in_sizes, int n_in,
                              void* d_out, int out_size) {
    const float* bigs[2] = {nullptr, nullptr};
    const float* smalls[2] = {nullptr, nullptr};
    int bi = 0, si = 0;
    for (int k = 0; k < n_in; k++) {
        if (in_sizes[k] == 256 * 256 * 256) { if (bi < 2) bigs[bi++] = (const float*)d_in[k]; }
        else                                { if (si < 2) smalls[si++] = (const float*)d_in[k]; }
    }
    const float* style_resp = bigs[0];
    const float* model_resp = bigs[1];
    const float* style_map  = smalls[0];
    const float* output_map = smalls[1];

    __half *pAh, *pAl, *pBh, *pBl;
    float* pSn;
    cudaGetSymbolAddress((void**)&pAh, g_Ah);
    cudaGetSymbolAddress((void**)&pAl, g_Al);
    cudaGetSymbolAddress((void**)&pBh, g_Bh);
    cudaGetSymbolAddress((void**)&pBl, g_Bl);
    cudaGetSymbolAddress((void**)&pSn, g_sninv);

    cudaFuncSetAttribute(gemm_hmma_argmax,
                         cudaFuncAttributeMaxDynamicSharedMemorySize, SMEM_TOTAL);

    init_kernel<<<(NP + 255) / 256, 256>>>();
    pack_kernel<<<NP, 256>>>(style_resp, style_map, pAh, pAl, pSn);      // style (+norms)
    pack_kernel<<<NP, 256>>>(model_resp, output_map, pBh, pBl, nullptr); // img
    gemm_hmma_argmax<<<dim3(NP / BNr, NP / BMr), 256, SMEM_TOTAL>>>();
    loss_kernel<<<N_REAL, 256>>>();
    finalize_kernel<<<1, 32>>>((float*)d_out);
}

// round 10
// speedup vs baseline: 8.5302x; 1.1014x over previous
#include <cuda_runtime.h>
#include <cuda_fp16.h>
#include <cstdint>

#define N_REAL 7225      // 85*85 patches
#define NP     7424      // padded: 58*128 = 29*256
#define D_REAL 2331      // 259*9
#define KCH    152       // k-chunks of 16 halves (32B): 19 stages of 8
#define LD     (KCH * 16)   // 2432 halves
#define NH     85

#define BMr 128          // style rows per CTA tile
#define BNr 256          // img rows per CTA tile
#define CPS 8            // chunks per stage
#define NST (KCH / CPS)  // 19 stages per tile
#define NTIL_X 29        // NP/BNr
#define NTIL 1682        // 29 * 58
#define GRIDC 148        // persistent CTAs (1 per SM)

// per-chunk layout inside a stage: Ah (4KB) then Bh (8KB)
#define CHUNK_B 12288
#define STAGE_B (CPS * CHUNK_B)          // 98304

// smem map
#define FULL_OFF 0                        // 2 mbarriers * 8B
#define TILE_OFF 1024
#define SMEM_TOTAL (TILE_OFF + 2 * STAGE_B)   // 197632

// ---------------- scratch (static device globals; no allocation) ------------
// chunk-major layout: [kchunk][row][16 halves], ldmatrix XOR swizzle baked in
__device__ __half g_Ah[(size_t)KCH * NP * 16];   // style hi
__device__ __half g_Bh[(size_t)KCH * NP * 16];   // img hi
__device__ float g_sninv[NP];                     // 1/||style_j||
__device__ float g_sn2[NP];                       // ||style_j||^2
__device__ float g_in2[NP];                       // ||img_i||^2
__device__ unsigned long long g_best[NP];
__device__ double g_acc;

// ---------------- helpers ----------------------------------------------------
__device__ __forceinline__ uint32_t smem_u32(const void* p) {
    uint32_t a;
    asm("{ .reg .u64 t; cvta.to.shared.u64 t, %1; cvt.u32.u64 %0, t; }" : "=r"(a) : "l"(p));
    return a;
}
__device__ __forceinline__ unsigned int encf(float f) {
    unsigned int u = __float_as_uint(f);
    unsigned int mask = (unsigned int)(-(int)(u >> 31)) | 0x80000000u;
    return u ^ mask;
}
__device__ __forceinline__ void ldsm4(uint32_t* r, uint32_t addr) {
    asm volatile("ldmatrix.sync.aligned.m8n8.x4.shared.b16 {%0,%1,%2,%3}, [%4];"
                 : "=r"(r[0]), "=r"(r[1]), "=r"(r[2]), "=r"(r[3]) : "r"(addr));
}
__device__ __forceinline__ void mma16816(float* c, const uint32_t* a, const uint32_t* b) {
    asm volatile(
        "mma.sync.aligned.m16n8k16.row.col.f32.f16.f16.f32 "
        "{%0,%1,%2,%3}, {%4,%5,%6,%7}, {%8,%9}, {%0,%1,%2,%3};"
        : "+f"(c[0]), "+f"(c[1]), "+f"(c[2]), "+f"(c[3])
        : "r"(a[0]), "r"(a[1]), "r"(a[2]), "r"(a[3]), "r"(b[0]), "r"(b[1]));
}
__device__ __forceinline__ void mbar_init(uint32_t mbar, uint32_t count) {
    asm volatile("mbarrier.init.shared.b64 [%0], %1;" :: "r"(mbar), "r"(count) : "memory");
}
__device__ __forceinline__ void mbar_expect_tx(uint32_t mbar, uint32_t bytes) {
    asm volatile("mbarrier.arrive.expect_tx.shared.b64 _, [%0], %1;"
                 :: "r"(mbar), "r"(bytes) : "memory");
}
__device__ __forceinline__ void mbar_wait(uint32_t mbar, uint32_t phase) {
    uint32_t done;
    asm volatile(
        "{\n\t.reg .pred p;\n\t"
        "mbarrier.try_wait.parity.acquire.cta.shared::cta.b64 p, [%1], %2;\n\t"
        "selp.b32 %0, 1, 0, p;\n\t}"
        : "=r"(done) : "r"(mbar), "r"(phase) : "memory");
    while (!done) {
        asm volatile(
            "{\n\t.reg .pred p;\n\t"
            "mbarrier.try_wait.parity.acquire.cta.shared::cta.b64 p, [%1], %2, 0x989680;\n\t"
            "selp.b32 %0, 1, 0, p;\n\t}"
            : "=r"(done) : "r"(mbar), "r"(phase) : "memory");
    }
}
__device__ __forceinline__ void bulkcp(uint32_t dst, const void* src, uint32_t bytes,
                                       uint32_t mbar) {
    asm volatile(
        "cp.async.bulk.shared::cluster.global.mbarrier::complete_tx::bytes [%0], [%1], %2, [%3];"
        :: "r"(dst), "l"(src), "r"(bytes), "r"(mbar) : "memory");
}
#define FENCE_PROXY() asm volatile("fence.proxy.async.shared::cta;" ::: "memory")

__device__ __forceinline__ float block_reduce_sum(float v) {
    __shared__ float sh[32];
    int lane = threadIdx.x & 31, w = threadIdx.x >> 5;
    #pragma unroll
    for (int o = 16; o; o >>= 1) v += __shfl_xor_sync(0xffffffffu, v, o);
    if (lane == 0) sh[w] = v;
    __syncthreads();
    if (w == 0) {
        v = (lane < (int)(blockDim.x >> 5)) ? sh[lane] : 0.f;
        #pragma unroll
        for (int o = 16; o; o >>= 1) v += __shfl_xor_sync(0xffffffffu, v, o);
    }
    return v;
}

// ---------------- init ------------------------------------------------------
__global__ void init_kernel() {
    int t = blockIdx.x * blockDim.x + threadIdx.x;
    if (t < NP) g_best[t] = 0ull;
    if (t == 0) g_acc = 0.0;
}

// ---------------- pack: fp16 hi + fused norms --------------------------------
__global__ void pack_kernel(const float* __restrict__ resp,
                            const float* __restrict__ map,
                            __half* __restrict__ hiDst,
                            float* __restrict__ snout,   // rsqrt(ss) or null
                            float* __restrict__ sqout) { // ss
    int i = blockIdx.x;
    int ph = i / NH, pw = i - ph * NH;
    bool valid = (i < N_REAL);
    int par = (i >> 2) & 1;
    float ss = 0.f;
    for (int d = threadIdx.x; d < LD; d += blockDim.x) {
        float v = 0.f;
        if (valid && d < D_REAL) {
            int c = d / 9, rem = d - c * 9;
            int py = rem / 3, px = rem - py * 3;
            int row = ph * 3 + py, col = pw * 3 + px;
            if (c < 256) {
                v = resp[((size_t)c * 256 + row) * 256 + col];
            } else {
                int m = c - 256;
                const float* mp = map + (size_t)m * 1024 * 1024 + (size_t)(row * 4) * 1024 + col * 4;
                float s = 0.f;
                #pragma unroll
                for (int u = 0; u < 4; u++)
                    #pragma unroll
                    for (int w = 0; w < 4; w++) s += mp[u * 1024 + w];
                v = s * (50.0f / 16.0f);
            }
        }
        int d15 = d & 15;
        size_t off = ((size_t)(d >> 4) * NP + i) * 16 +
                     ((((d15 >> 3) ^ par) << 3) | (d15 & 7));
        hiDst[off] = __float2half_rn(v);
        ss += v * v;
    }
    ss = block_reduce_sum(ss);
    if (threadIdx.x == 0) {
        if (snout) snout[i] = (i < N_REAL) ? rsqrtf(ss) : 0.f;
        if (sqout) sqout[i] = ss;
    }
}

// ---------------- persistent HMMA GEMM + fused argmax ------------------------
__device__ __forceinline__ void issue_stage(uint32_t sb, int gst, int bid) {
    int s = gst & 1;
    int tmine = gst / NST;
    int st = gst - tmine * NST;
    int tid = bid + tmine * GRIDC;
    int ty = tid / NTIL_X;
    int i0 = ty * BMr;
    int j0 = (tid - ty * NTIL_X) * BNr;
    uint32_t full = sb + FULL_OFF + s * 8;
    uint32_t stg = sb + TILE_OFF + s * STAGE_B;
    mbar_expect_tx(full, STAGE_B);
    #pragma unroll
    for (int q = 0; q < CPS; q++) {
        int c = st * CPS + q;
        bulkcp(stg + q * CHUNK_B,        g_Ah + ((size_t)c * NP + i0) * 16, 4096, full);
        bulkcp(stg + q * CHUNK_B + 4096, g_Bh + ((size_t)c * NP + j0) * 16, 8192, full);
    }
}

struct Frag {
    uint32_t a[4][4];
    uint32_t b[8][2];
};
__device__ __forceinline__ void load_frags(Frag& f, uint32_t cb,
                                           const uint32_t* offA, const uint32_t* offB) {
    #pragma unroll
    for (int mt = 0; mt < 4; mt++) ldsm4(f.a[mt], cb + offA[mt]);
    #pragma unroll
    for (int pt = 0; pt < 4; pt++) {
        uint32_t r[4];
        ldsm4(r, cb + 4096 + offB[pt]);
        f.b[2 * pt][0] = r[0]; f.b[2 * pt][1] = r[1];
        f.b[2 * pt + 1][0] = r[2]; f.b[2 * pt + 1][1] = r[3];
    }
}

__global__ void __launch_bounds__(256, 1)
gemm_hmma_persistent() {
    extern __shared__ char smem[];
    uint32_t sb = smem_u32(smem);
    int t = threadIdx.x, lane = t & 31, w = t >> 5;
    int bid = blockIdx.x;
    int nMine = (NTIL - bid + GRIDC - 1) / GRIDC;
    int totalStages = nMine * NST;

    if (t < 2) mbar_init(sb + FULL_OFF + t * 8, 1);
    __syncthreads();
    if (t == 0) {
        FENCE_PROXY();
        issue_stage(sb, 0, bid);
        issue_stage(sb, 1, bid);
    }

    int m0 = (w >> 2) * 64;   // warp row offset (0/64)
    int n0 = (w & 3) * 64;    // warp col offset (0/64/128/192)

    uint32_t offA[4], offB[4];
    #pragma unroll
    for (int mt = 0; mt < 4; mt++) {
        int row = m0 + mt * 16 + (lane & 15);
        int seg = lane >> 4;
        offA[mt] = (uint32_t)(row * 32 + ((seg ^ ((row >> 2) & 1)) << 4));
    }
    #pragma unroll
    for (int pt = 0; pt < 4; pt++) {
        int rr = n0 + pt * 16 + ((lane >> 4) << 3) + (lane & 7);
        int seg = (lane >> 3) & 1;
        offB[pt] = (uint32_t)(rr * 32 + ((seg ^ ((rr >> 2) & 1)) << 4));
    }

    float acc[4][8][4];
    #pragma unroll
    for (int a = 0; a < 4; a++)
        #pragma unroll
        for (int b = 0; b < 8; b++)
            #pragma unroll
            for (int q = 0; q < 4; q++) acc[a][b][q] = 0.f;

    Frag frag[2];
    int phase[2] = {0, 0};

    // prologue: wait stage 0, load its chunk-0 fragments
    mbar_wait(sb + FULL_OFF + 0, 0);
    phase[0] ^= 1;
    load_frags(frag[0], sb + TILE_OFF + 0, offA, offB);

    int cur = 0, gst = 0;
    for (int tt = 0; tt < nMine; tt++) {
        int tid = bid + tt * GRIDC;
        int ty = tid / NTIL_X;
        int i0 = ty * BMr;
        int j0 = (tid - ty * NTIL_X) * BNr;

        for (int st = 0; st < NST; st++, gst++) {
            int s = gst & 1;
            uint32_t stg = sb + TILE_OFF + s * STAGE_B;
            #pragma unroll
            for (int q = 0; q < CPS; q++) {
                bool lastAll = (gst == totalStages - 1) && (q == CPS - 1);
                if (!lastAll) {
                    if (q < CPS - 1) {
                        load_frags(frag[cur ^ 1], stg + (q + 1) * CHUNK_B, offA, offB);
                    } else {
                        int ns = (gst + 1) & 1;
                        mbar_wait(sb + FULL_OFF + ns * 8, phase[ns]);
                        phase[ns] ^= 1;
                        load_frags(frag[cur ^ 1], sb + TILE_OFF + ns * STAGE_B, offA, offB);
                    }
                }
                if (q == CPS - 1) {
                    __syncthreads();   // all warps done with ldsm from slot s
                    if (t == 0 && gst + 2 < totalStages) {
                        FENCE_PROXY();
                        issue_stage(sb, gst + 2, bid);
                    }
                }
                #pragma unroll
                for (int mt = 0; mt < 4; mt++)
                    #pragma unroll
                    for (int nt = 0; nt < 8; nt++)
                        mma16816(acc[mt][nt], frag[cur].a[mt], frag[cur].b[nt]);
                cur ^= 1;
            }
        }

        // ---- tile epilogue: scale by sninv[j], per-row argmax, atomicMax ----
        int qlane = lane & 3;
        #pragma unroll
        for (int mt = 0; mt < 4; mt++) {
            #pragma unroll
            for (int h = 0; h < 2; h++) {
                unsigned long long key = 0ull;
                #pragma unroll
                for (int nt = 0; nt < 8; nt++) {
                    #pragma unroll
                    for (int e = 0; e < 2; e++) {
                        int jc = n0 + nt * 8 + 2 * qlane + e;
                        int j = j0 + jc;
                        float v = acc[mt][nt][2 * h + e] * __ldg(&g_sninv[j]);
                        if (j < N_REAL) {
                            unsigned long long k =
                                ((unsigned long long)encf(v) << 32) |
                                (unsigned long long)(0xFFFFFFFFu - (unsigned)j);
                            if (k > key) key = k;
                        }
                    }
                }
                #pragma unroll
                for (int o = 1; o < 4; o <<= 1) {
                    unsigned long long other = __shfl_xor_sync(0xffffffffu, key, o);
                    if (other > key) key = other;
                }
                int m = i0 + m0 + mt * 16 + h * 8 + (lane >> 2);
                if (qlane == 0 && m < N_REAL) atomicMax(&g_best[m], key);
                // zero this slice of acc for next tile
                #pragma unroll
                for (int nt = 0; nt < 8; nt++) {
                    acc[mt][nt][2 * h + 0] = 0.f;
                    acc[mt][nt][2 * h + 1] = 0.f;
                }
            }
        }
    }
}

// ---------------- loss: gather dot(img_i, style_nearest) + exact norms ------
__global__ void loss_kernel() {
    int i = blockIdx.x;  // img patch index
    unsigned long long key = g_best[i];
    unsigned int n = 0xFFFFFFFFu - (unsigned int)(key & 0xFFFFFFFFull);
    int pi = (i >> 2) & 1, pn = ((int)n >> 2) & 1;
    float dot = 0.f;
    for (int g = threadIdx.x; g < LD / 8; g += blockDim.x) {
        int c = g >> 1, seg = g & 1;
        const __half2* ih = (const __half2*)(g_Bh + ((size_t)c * NP + i) * 16 +
                                             (size_t)((seg ^ pi) << 3));
        const __half2* sh2 = (const __half2*)(g_Ah + ((size_t)c * NP + n) * 16 +
                                              (size_t)((seg ^ pn) << 3));
        #pragma unroll
        for (int q = 0; q < 4; q++) {
            float2 a = __half22float2(ih[q]);
            float2 b = __half22float2(sh2[q]);
            dot += a.x * b.x + a.y * b.y;
        }
    }
    dot = block_reduce_sum(dot);
    if (threadIdx.x == 0) {
        float s = g_in2[i] + g_sn2[n] - 2.f * dot;
        atomicAdd(&g_acc, (double)s);
    }
}

__global__ void finalize_kernel(float* out) {
    if (threadIdx.x == 0)
        out[0] = (float)(g_acc / ((double)D_REAL * (double)N_REAL));
}

// ---------------- launch ----------------------------------------------------
extern "C" void kernel_launch(void* const* d_in, const int* in_sizes, int n_in,
                              void* d_out, int out_size) {
    const float* bigs[2] = {nullptr, nullptr};
    const float* smalls[2] = {nullptr, nullptr};
    int bi = 0, si = 0;
    for (int k = 0; k < n_in; k++) {
        if (in_sizes[k] == 256 * 256 * 256) { if (bi < 2) bigs[bi++] = (const float*)d_in[k]; }
        else                                { if (si < 2) smalls[si++] = (const float*)d_in[k]; }
    }
    const float* style_resp = bigs[0];
    const float* model_resp = bigs[1];
    const float* style_map  = smalls[0];
    const float* output_map = smalls[1];

    __half *pAh, *pBh;
    float *pSn, *pSn2, *pIn2;
    cudaGetSymbolAddress((void**)&pAh, g_Ah);
    cudaGetSymbolAddress((void**)&pBh, g_Bh);
    cudaGetSymbolAddress((void**)&pSn, g_sninv);
    cudaGetSymbolAddress((void**)&pSn2, g_sn2);
    cudaGetSymbolAddress((void**)&pIn2, g_in2);

    cudaFuncSetAttribute(gemm_hmma_persistent,
                         cudaFuncAttributeMaxDynamicSharedMemorySize, SMEM_TOTAL);

    init_kernel<<<(NP + 255) / 256, 256>>>();
    pack_kernel<<<NP, 256>>>(style_resp, style_map, pAh, pSn, pSn2);      // style
    pack_kernel<<<NP, 256>>>(model_resp, output_map, pBh, nullptr, pIn2); // img
    gemm_hmma_persistent<<<GRIDC, 256, SMEM_TOTAL>>>();
    loss_kernel<<<N_REAL, 256>>>();
    finalize_kernel<<<1, 32>>>((float*)d_out);
}

// round 11
// speedup vs baseline: 8.7851x; 1.0299x over previous
#include <cuda_runtime.h>
#include <cuda_fp16.h>
#include <cstdint>

#define N_REAL 7225      // 85*85 patches
#define NP     7424      // padded: 58*128 = 29*256
#define D_REAL 2331      // 259*9
#define KCH    146       // k-chunks of 16 halves (32B): 18 stages of 8 + 1 of 2
#define LD     (KCH * 16)   // 2336 halves
#define NH     85

#define BMr 128          // style rows per CTA tile
#define BNr 256          // img rows per CTA tile
#define CPS 8            // chunks per full stage
#define NST 19           // stages per tile (18 full + 1 partial)
#define LASTQ (KCH - (NST - 1) * CPS)   // 2
#define NTIL_X 29        // NP/BNr
#define NTIL 1682        // 29 * 58
#define GRIDC 148        // persistent CTAs (1 per SM)

// per-chunk layout inside a stage: Ah (4KB) then Bh (8KB)
#define CHUNK_B 12288
#define STAGE_B (CPS * CHUNK_B)          // 98304 (slot size; partial stage uses prefix)

// smem map
#define FULL_OFF 0                        // 2 mbarriers * 8B
#define TILE_OFF 1024
#define SMEM_TOTAL (TILE_OFF + 2 * STAGE_B)   // 197632

// ---------------- scratch (static device globals; no allocation) ------------
// chunk-major layout: [kchunk][row][16 halves], ldmatrix XOR swizzle baked in
__device__ __half g_Ah[(size_t)KCH * NP * 16];   // style hi
__device__ __half g_Bh[(size_t)KCH * NP * 16];   // img hi
__device__ float g_sninv[NP];                     // 1/||style_j||
__device__ float g_sn2[NP];                       // ||style_j||^2
__device__ float g_in2[NP];                       // ||img_i||^2
__device__ unsigned long long g_best[NP];
__device__ double g_acc;

// ---------------- helpers ----------------------------------------------------
__device__ __forceinline__ uint32_t smem_u32(const void* p) {
    uint32_t a;
    asm("{ .reg .u64 t; cvta.to.shared.u64 t, %1; cvt.u32.u64 %0, t; }" : "=r"(a) : "l"(p));
    return a;
}
__device__ __forceinline__ unsigned int encf(float f) {
    unsigned int u = __float_as_uint(f);
    unsigned int mask = (unsigned int)(-(int)(u >> 31)) | 0x80000000u;
    return u ^ mask;
}
__device__ __forceinline__ void ldsm4(uint32_t* r, uint32_t addr) {
    asm volatile("ldmatrix.sync.aligned.m8n8.x4.shared.b16 {%0,%1,%2,%3}, [%4];"
                 : "=r"(r[0]), "=r"(r[1]), "=r"(r[2]), "=r"(r[3]) : "r"(addr));
}
__device__ __forceinline__ void mma16816(float* c, const uint32_t* a, const uint32_t* b) {
    asm volatile(
        "mma.sync.aligned.m16n8k16.row.col.f32.f16.f16.f32 "
        "{%0,%1,%2,%3}, {%4,%5,%6,%7}, {%8,%9}, {%0,%1,%2,%3};"
        : "+f"(c[0]), "+f"(c[1]), "+f"(c[2]), "+f"(c[3])
        : "r"(a[0]), "r"(a[1]), "r"(a[2]), "r"(a[3]), "r"(b[0]), "r"(b[1]));
}
__device__ __forceinline__ void mbar_init(uint32_t mbar, uint32_t count) {
    asm volatile("mbarrier.init.shared.b64 [%0], %1;" :: "r"(mbar), "r"(count) : "memory");
}
__device__ __forceinline__ void mbar_expect_tx(uint32_t mbar, uint32_t bytes) {
    asm volatile("mbarrier.arrive.expect_tx.shared.b64 _, [%0], %1;"
                 :: "r"(mbar), "r"(bytes) : "memory");
}
__device__ __forceinline__ void mbar_wait(uint32_t mbar, uint32_t phase) {
    uint32_t done;
    asm volatile(
        "{\n\t.reg .pred p;\n\t"
        "mbarrier.try_wait.parity.acquire.cta.shared::cta.b64 p, [%1], %2;\n\t"
        "selp.b32 %0, 1, 0, p;\n\t}"
        : "=r"(done) : "r"(mbar), "r"(phase) : "memory");
    while (!done) {
        asm volatile(
            "{\n\t.reg .pred p;\n\t"
            "mbarrier.try_wait.parity.acquire.cta.shared::cta.b64 p, [%1], %2, 0x989680;\n\t"
            "selp.b32 %0, 1, 0, p;\n\t}"
            : "=r"(done) : "r"(mbar), "r"(phase) : "memory");
    }
}
__device__ __forceinline__ void bulkcp(uint32_t dst, const void* src, uint32_t bytes,
                                       uint32_t mbar) {
    asm volatile(
        "cp.async.bulk.shared::cluster.global.mbarrier::complete_tx::bytes [%0], [%1], %2, [%3];"
        :: "r"(dst), "l"(src), "r"(bytes), "r"(mbar) : "memory");
}
#define FENCE_PROXY() asm volatile("fence.proxy.async.shared::cta;" ::: "memory")

__device__ __forceinline__ float block_reduce_sum(float v) {
    __shared__ float sh[32];
    int lane = threadIdx.x & 31, w = threadIdx.x >> 5;
    #pragma unroll
    for (int o = 16; o; o >>= 1) v += __shfl_xor_sync(0xffffffffu, v, o);
    if (lane == 0) sh[w] = v;
    __syncthreads();
    if (w == 0) {
        v = (lane < (int)(blockDim.x >> 5)) ? sh[lane] : 0.f;
        #pragma unroll
        for (int o = 16; o; o >>= 1) v += __shfl_xor_sync(0xffffffffu, v, o);
    }
    return v;
}

// ---------------- init ------------------------------------------------------
__global__ void init_kernel() {
    int t = blockIdx.x * blockDim.x + threadIdx.x;
    if (t < NP) g_best[t] = 0ull;
    if (t == 0) g_acc = 0.0;
}

// ---------------- pack: 4 patches/block, coalesced reads + fused norms ------
__global__ void pack_kernel(const float* __restrict__ resp,
                            const float* __restrict__ map,
                            __half* __restrict__ hiDst,
                            float* __restrict__ snout,   // rsqrt(ss) or null
                            float* __restrict__ sqout) { // ss
    __shared__ float red[8][4];
    int t = threadIdx.x;
    int p = t & 3;
    int i = blockIdx.x * 4 + p;
    int ph = i / NH, pw = i - ph * NH;
    bool valid = (i < N_REAL);
    int par = (i >> 2) & 1;
    float ss = 0.f;
    for (int d = (t >> 2); d < LD; d += 64) {
        float v = 0.f;
        if (valid && d < D_REAL) {
            int c = d / 9, rem = d - c * 9;
            int py = rem / 3, px = rem - py * 3;
            int row = ph * 3 + py, col = pw * 3 + px;
            if (c < 256) {
                v = resp[((size_t)c * 256 + row) * 256 + col];
            } else {
                int m = c - 256;
                const float* mp = map + (size_t)m * 1024 * 1024 + (size_t)(row * 4) * 1024 + col * 4;
                float s = 0.f;
                #pragma unroll
                for (int u = 0; u < 4; u++)
                    #pragma unroll
                    for (int w = 0; w < 4; w++) s += mp[u * 1024 + w];
                v = s * (50.0f / 16.0f);
            }
        }
        int d15 = d & 15;
        size_t off = ((size_t)(d >> 4) * NP + i) * 16 +
                     ((((d15 >> 3) ^ par) << 3) | (d15 & 7));
        hiDst[off] = __float2half_rn(v);
        ss += v * v;
    }
    // reduce over lanes with the same p (xor offsets preserve lane&3)
    #pragma unroll
    for (int o = 4; o < 32; o <<= 1) ss += __shfl_xor_sync(0xffffffffu, ss, o);
    int lane = t & 31, w = t >> 5;
    if (lane < 4) red[w][lane] = ss;
    __syncthreads();
    if (t < 32) {
        int pp = t & 3, ww = t >> 2;   // ww 0..7
        float v2 = red[ww][pp];
        #pragma unroll
        for (int o = 4; o < 32; o <<= 1) v2 += __shfl_xor_sync(0xffffffffu, v2, o);
        if (t < 4) {
            int ii = blockIdx.x * 4 + pp;
            if (snout) snout[ii] = (ii < N_REAL) ? rsqrtf(v2) : 0.f;
            if (sqout) sqout[ii] = v2;
        }
    }
}

// ---------------- persistent HMMA GEMM + fused argmax ------------------------
__device__ __forceinline__ void issue_stage(uint32_t sb, int gst, int bid) {
    int s = gst & 1;
    int tmine = gst / NST;
    int st = gst - tmine * NST;
    int nq = (st == NST - 1) ? LASTQ : CPS;
    int tid = bid + tmine * GRIDC;
    int ty = tid / NTIL_X;
    int i0 = ty * BMr;
    int j0 = (tid - ty * NTIL_X) * BNr;
    uint32_t full = sb + FULL_OFF + s * 8;
    uint32_t stg = sb + TILE_OFF + s * STAGE_B;
    mbar_expect_tx(full, (uint32_t)(nq * CHUNK_B));
    for (int q = 0; q < nq; q++) {
        int c = st * CPS + q;
        bulkcp(stg + q * CHUNK_B,        g_Ah + ((size_t)c * NP + i0) * 16, 4096, full);
        bulkcp(stg + q * CHUNK_B + 4096, g_Bh + ((size_t)c * NP + j0) * 16, 8192, full);
    }
}

struct Frag {
    uint32_t a[4][4];
    uint32_t b[8][2];
};
__device__ __forceinline__ void load_frags(Frag& f, uint32_t cb,
                                           const uint32_t* offA, const uint32_t* offB) {
    #pragma unroll
    for (int mt = 0; mt < 4; mt++) ldsm4(f.a[mt], cb + offA[mt]);
    #pragma unroll
    for (int pt = 0; pt < 4; pt++) {
        uint32_t r[4];
        ldsm4(r, cb + 4096 + offB[pt]);
        f.b[2 * pt][0] = r[0]; f.b[2 * pt][1] = r[1];
        f.b[2 * pt + 1][0] = r[2]; f.b[2 * pt + 1][1] = r[3];
    }
}

template <int NQ>
__device__ __forceinline__ void process_stage(
    uint32_t sb, int& gst, int totalStages, int bid,
    Frag* frag, int& cur, int* phase,
    const uint32_t* offA, const uint32_t* offB,
    float (*acc)[8][4], int t)
{
    int s = gst & 1;
    uint32_t stg = sb + TILE_OFF + s * STAGE_B;
    #pragma unroll
    for (int q = 0; q < NQ; q++) {
        bool lastAll = (gst == totalStages - 1) && (q == NQ - 1);
        if (!lastAll) {
            if (q < NQ - 1) {
                load_frags(frag[cur ^ 1], stg + (q + 1) * CHUNK_B, offA, offB);
            } else {
                int ns = (gst + 1) & 1;
                mbar_wait(sb + FULL_OFF + ns * 8, phase[ns]);
                phase[ns] ^= 1;
                load_frags(frag[cur ^ 1], sb + TILE_OFF + ns * STAGE_B, offA, offB);
            }
        }
        if (q == NQ - 1) {
            __syncthreads();   // all warps done with ldsm from slot s
            if (t == 0 && gst + 2 < totalStages) {
                FENCE_PROXY();
                issue_stage(sb, gst + 2, bid);
            }
        }
        #pragma unroll
        for (int mt = 0; mt < 4; mt++)
            #pragma unroll
            for (int nt = 0; nt < 8; nt++)
                mma16816(acc[mt][nt], frag[cur].a[mt], frag[cur].b[nt]);
        cur ^= 1;
    }
    gst++;
}

__global__ void __launch_bounds__(256, 1)
gemm_hmma_persistent() {
    extern __shared__ char smem[];
    uint32_t sb = smem_u32(smem);
    int t = threadIdx.x, lane = t & 31, w = t >> 5;
    int bid = blockIdx.x;
    int nMine = (NTIL - bid + GRIDC - 1) / GRIDC;
    int totalStages = nMine * NST;

    if (t < 2) mbar_init(sb + FULL_OFF + t * 8, 1);
    __syncthreads();
    if (t == 0) {
        FENCE_PROXY();
        issue_stage(sb, 0, bid);
        issue_stage(sb, 1, bid);
    }

    int m0 = (w >> 2) * 64;   // warp row offset (0/64)
    int n0 = (w & 3) * 64;    // warp col offset (0/64/128/192)

    uint32_t offA[4], offB[4];
    #pragma unroll
    for (int mt = 0; mt < 4; mt++) {
        int row = m0 + mt * 16 + (lane & 15);
        int seg = lane >> 4;
        offA[mt] = (uint32_t)(row * 32 + ((seg ^ ((row >> 2) & 1)) << 4));
    }
    #pragma unroll
    for (int pt = 0; pt < 4; pt++) {
        int rr = n0 + pt * 16 + ((lane >> 4) << 3) + (lane & 7);
        int seg = (lane >> 3) & 1;
        offB[pt] = (uint32_t)(rr * 32 + ((seg ^ ((rr >> 2) & 1)) << 4));
    }

    float acc[4][8][4];
    #pragma unroll
    for (int a = 0; a < 4; a++)
        #pragma unroll
        for (int b = 0; b < 8; b++)
            #pragma unroll
            for (int q = 0; q < 4; q++) acc[a][b][q] = 0.f;

    Frag frag[2];
    int phase[2] = {0, 0};

    // prologue: wait stage 0, load its chunk-0 fragments
    mbar_wait(sb + FULL_OFF + 0, 0);
    phase[0] ^= 1;
    load_frags(frag[0], sb + TILE_OFF + 0, offA, offB);

    int cur = 0, gst = 0;
    for (int tt = 0; tt < nMine; tt++) {
        int tid = bid + tt * GRIDC;
        int ty = tid / NTIL_X;
        int i0 = ty * BMr;
        int j0 = (tid - ty * NTIL_X) * BNr;

        #pragma unroll 1
        for (int st = 0; st < NST - 1; st++)
            process_stage<CPS>(sb, gst, totalStages, bid, frag, cur, phase,
                               offA, offB, acc, t);
        process_stage<LASTQ>(sb, gst, totalStages, bid, frag, cur, phase,
                             offA, offB, acc, t);

        // ---- tile epilogue: scale by sninv[j], per-row argmax, atomicMax ----
        int qlane = lane & 3;
        #pragma unroll
        for (int mt = 0; mt < 4; mt++) {
            #pragma unroll
            for (int h = 0; h < 2; h++) {
                unsigned long long key = 0ull;
                #pragma unroll
                for (int nt = 0; nt < 8; nt++) {
                    #pragma unroll
                    for (int e = 0; e < 2; e++) {
                        int jc = n0 + nt * 8 + 2 * qlane + e;
                        int j = j0 + jc;
                        float v = acc[mt][nt][2 * h + e] * __ldg(&g_sninv[j]);
                        if (j < N_REAL) {
                            unsigned long long k =
                                ((unsigned long long)encf(v) << 32) |
                                (unsigned long long)(0xFFFFFFFFu - (unsigned)j);
                            if (k > key) key = k;
                        }
                    }
                }
                #pragma unroll
                for (int o = 1; o < 4; o <<= 1) {
                    unsigned long long other = __shfl_xor_sync(0xffffffffu, key, o);
                    if (other > key) key = other;
                }
                int m = i0 + m0 + mt * 16 + h * 8 + (lane >> 2);
                if (qlane == 0 && m < N_REAL) atomicMax(&g_best[m], key);
                // zero this slice of acc for next tile
                #pragma unroll
                for (int nt = 0; nt < 8; nt++) {
                    acc[mt][nt][2 * h + 0] = 0.f;
                    acc[mt][nt][2 * h + 1] = 0.f;
                }
            }
        }
    }
}

// ---------------- loss: gather dot(img_i, style_nearest) + exact norms ------
__global__ void loss_kernel() {
    int i = blockIdx.x;  // img patch index
    unsigned long long key = g_best[i];
    unsigned int n = 0xFFFFFFFFu - (unsigned int)(key & 0xFFFFFFFFull);
    int pi = (i >> 2) & 1, pn = ((int)n >> 2) & 1;
    float dot = 0.f;
    for (int g = threadIdx.x; g < LD / 8; g += blockDim.x) {
        int c = g >> 1, seg = g & 1;
        const __half2* ih = (const __half2*)(g_Bh + ((size_t)c * NP + i) * 16 +
                                             (size_t)((seg ^ pi) << 3));
        const __half2* sh2 = (const __half2*)(g_Ah + ((size_t)c * NP + n) * 16 +
                                              (size_t)((seg ^ pn) << 3));
        #pragma unroll
        for (int q = 0; q < 4; q++) {
            float2 a = __half22float2(ih[q]);
            float2 b = __half22float2(sh2[q]);
            dot += a.x * b.x + a.y * b.y;
        }
    }
    dot = block_reduce_sum(dot);
    if (threadIdx.x == 0) {
        float s = g_in2[i] + g_sn2[n] - 2.f * dot;
        atomicAdd(&g_acc, (double)s);
    }
}

__global__ void finalize_kernel(float* out) {
    if (threadIdx.x == 0)
        out[0] = (float)(g_acc / ((double)D_REAL * (double)N_REAL));
}

// ---------------- launch ----------------------------------------------------
extern "C" void kernel_launch(void* const* d_in, const int* in_sizes, int n_in,
                              void* d_out, int out_size) {
    const float* bigs[2] = {nullptr, nullptr};
    const float* smalls[2] = {nullptr, nullptr};
    int bi = 0, si = 0;
    for (int k = 0; k < n_in; k++) {
        if (in_sizes[k] == 256 * 256 * 256) { if (bi < 2) bigs[bi++] = (const float*)d_in[k]; }
        else                                { if (si < 2) smalls[si++] = (const float*)d_in[k]; }
    }
    const float* style_resp = bigs[0];
    const float* model_resp = bigs[1];
    const float* style_map  = smalls[0];
    const float* output_map = smalls[1];

    __half *pAh, *pBh;
    float *pSn, *pSn2, *pIn2;
    cudaGetSymbolAddress((void**)&pAh, g_Ah);
    cudaGetSymbolAddress((void**)&pBh, g_Bh);
    cudaGetSymbolAddress((void**)&pSn, g_sninv);
    cudaGetSymbolAddress((void**)&pSn2, g_sn2);
    cudaGetSymbolAddress((void**)&pIn2, g_in2);

    cudaFuncSetAttribute(gemm_hmma_persistent,
                         cudaFuncAttributeMaxDynamicSharedMemorySize, SMEM_TOTAL);

    init_kernel<<<(NP + 255) / 256, 256>>>();
    pack_kernel<<<NP / 4, 256>>>(style_resp, style_map, pAh, pSn, pSn2);      // style
    pack_kernel<<<NP / 4, 256>>>(model_resp, output_map, pBh, nullptr, pIn2); // img
    gemm_hmma_persistent<<<GRIDC, 256, SMEM_TOTAL>>>();
    loss_kernel<<<N_REAL, 256>>>();
    finalize_kernel<<<1, 32>>>((float*)d_out);
}